// round 3
// baseline (speedup 1.0000x reference)
#include <cuda_runtime.h>

#define TT 1024      // timesteps
#define DD 1024      // model dim
#define A3 3072      // 3 * attention_dim
#define FF 4096      // feedforward dim
#define BT 2048      // B * T rows
#define NBH 32       // B * H batched heads

// ---------------- scratch (device globals; no allocations allowed) ----------------
__device__ float g_qkv_u[BT * A3];
__device__ float g_qkv_v[BT * A3];
__device__ float g_G[NBH * 64 * 64];
__device__ float g_H[NBH * 64 * 64];
__device__ float g_qp[BT * DD];
__device__ float g_comb[(size_t)NBH * TT * TT];
__device__ float g_attn[BT * DD];
__device__ float g_proj[BT * DD];
__device__ float g_o1[BT * DD];
__device__ float g_ffn[BT * FF];
__device__ float g_f2[BT * DD];

// ---------------- generic 128x128x8 SGEMM, row-major, optional bias/relu ----------
// grid.x = N/128, grid.y = M/128, grid.z = batch
__global__ void __launch_bounds__(256) sgemm128(
    const float* __restrict__ A, const float* __restrict__ B, float* __restrict__ C,
    int lda, int ldb, int ldc, int K,
    size_t sA, size_t sB, size_t sC,
    const float* __restrict__ bias, int relu)
{
    int z = blockIdx.z;
    A += (size_t)z * sA; B += (size_t)z * sB; C += (size_t)z * sC;

    __shared__ float As[8][128];
    __shared__ float Bs[8][128];

    int tid = threadIdx.x;
    int tx = tid & 15, ty = tid >> 4;
    int row0 = blockIdx.y * 128, col0 = blockIdx.x * 128;

    int aRow = tid >> 1, aCol = (tid & 1) * 4;
    int bRow = tid >> 5, bCol = (tid & 31) * 4;
    const float* Aptr = A + (size_t)(row0 + aRow) * lda + aCol;
    const float* Bptr = B + (size_t)bRow * ldb + col0 + bCol;

    float acc[8][8] = {};

    for (int k0 = 0; k0 < K; k0 += 8) {
        float4 av = *(const float4*)(Aptr + k0);
        float4 bv = *(const float4*)(Bptr + (size_t)k0 * ldb);
        As[aCol + 0][aRow] = av.x;
        As[aCol + 1][aRow] = av.y;
        As[aCol + 2][aRow] = av.z;
        As[aCol + 3][aRow] = av.w;
        *(float4*)&Bs[bRow][bCol] = bv;
        __syncthreads();

        #pragma unroll
        for (int kk = 0; kk < 8; kk++) {
            float ra[8], rb[8];
            #pragma unroll
            for (int i = 0; i < 8; i++) ra[i] = As[kk][ty * 8 + i];
            #pragma unroll
            for (int j = 0; j < 8; j++) rb[j] = Bs[kk][tx * 8 + j];
            #pragma unroll
            for (int i = 0; i < 8; i++)
                #pragma unroll
                for (int j = 0; j < 8; j++)
                    acc[i][j] = fmaf(ra[i], rb[j], acc[i][j]);
        }
        __syncthreads();
    }

    #pragma unroll
    for (int i = 0; i < 8; i++) {
        size_t r = (size_t)(row0 + ty * 8 + i);
        #pragma unroll
        for (int jj = 0; jj < 8; jj += 4) {
            int c = col0 + tx * 8 + jj;
            float4 v;
            v.x = acc[i][jj]; v.y = acc[i][jj + 1]; v.z = acc[i][jj + 2]; v.w = acc[i][jj + 3];
            if (bias) {
                float4 bb = *(const float4*)&bias[c];
                v.x += bb.x; v.y += bb.y; v.z += bb.z; v.w += bb.w;
            }
            if (relu) {
                v.x = fmaxf(v.x, 0.f); v.y = fmaxf(v.y, 0.f);
                v.z = fmaxf(v.z, 0.f); v.w = fmaxf(v.w, 0.f);
            }
            *(float4*)&C[r * ldc + c] = v;
        }
    }
}

// -------- G = K^T diag(mask) Q  per (b,h), 64x64 output. grid.x = 32 -------------
__global__ void __launch_bounds__(256) gmat_kernel(
    const float* __restrict__ qkv, const int* __restrict__ mask, float* __restrict__ G)
{
    int z = blockIdx.x; int b = z >> 4; int h = z & 15;
    const float* Kb = qkv + (size_t)b * TT * A3 + 1024 + h * 64;
    const float* Qb = qkv + (size_t)b * TT * A3 + h * 64;
    __shared__ float Ks[64][65];
    __shared__ float Qs[64][65];
    int tid = threadIdx.x, tx = tid & 15, ty = tid >> 4;
    float acc[4][4] = {};

    for (int t0 = 0; t0 < TT; t0 += 64) {
        #pragma unroll
        for (int l = 0; l < 4; l++) {
            int lin = tid + l * 256; int r = lin >> 4; int c4 = (lin & 15) * 4;
            int trow = t0 + r;
            float mk = mask[b * TT + trow] ? 1.0f : 0.0f;
            float4 kv = *(const float4*)&Kb[(size_t)trow * A3 + c4];
            Ks[r][c4] = kv.x * mk; Ks[r][c4 + 1] = kv.y * mk;
            Ks[r][c4 + 2] = kv.z * mk; Ks[r][c4 + 3] = kv.w * mk;
            float4 qv = *(const float4*)&Qb[(size_t)trow * A3 + c4];
            Qs[r][c4] = qv.x; Qs[r][c4 + 1] = qv.y; Qs[r][c4 + 2] = qv.z; Qs[r][c4 + 3] = qv.w;
        }
        __syncthreads();
        #pragma unroll
        for (int t = 0; t < 64; t++) {
            float ra[4], rb[4];
            #pragma unroll
            for (int i = 0; i < 4; i++) ra[i] = Ks[t][ty * 4 + i];
            #pragma unroll
            for (int j = 0; j < 4; j++) rb[j] = Qs[t][tx * 4 + j];
            #pragma unroll
            for (int i = 0; i < 4; i++)
                #pragma unroll
                for (int j = 0; j < 4; j++) acc[i][j] = fmaf(ra[i], rb[j], acc[i][j]);
        }
        __syncthreads();
    }
    float* Gz = G + z * 4096;
    #pragma unroll
    for (int i = 0; i < 4; i++) {
        float4 o; o.x = acc[i][0]; o.y = acc[i][1]; o.z = acc[i][2]; o.w = acc[i][3];
        *(float4*)&Gz[(ty * 4 + i) * 64 + tx * 4] = o;
    }
}

// -------- Q' = Q @ G per (b,h). grid = (16 m-tiles, 32 bh) ------------------------
__global__ void __launch_bounds__(256) qprime_kernel(
    const float* __restrict__ qkv, const float* __restrict__ G, float* __restrict__ qp)
{
    int z = blockIdx.y; int b = z >> 4; int h = z & 15;
    const float* Qb = qkv + (size_t)b * TT * A3 + h * 64;
    const float* Gz = G + z * 4096;
    float* O = qp + (size_t)b * TT * DD + h * 64;
    __shared__ float Qs[64][65];
    __shared__ float Gs[64][65];
    int tid = threadIdx.x, tx = tid & 15, ty = tid >> 4;
    int i0 = blockIdx.x * 64;
    #pragma unroll
    for (int l = 0; l < 4; l++) {
        int lin = tid + l * 256; int r = lin >> 4; int c4 = (lin & 15) * 4;
        float4 qv = *(const float4*)&Qb[(size_t)(i0 + r) * A3 + c4];
        Qs[r][c4] = qv.x; Qs[r][c4 + 1] = qv.y; Qs[r][c4 + 2] = qv.z; Qs[r][c4 + 3] = qv.w;
        float4 gv = *(const float4*)&Gz[r * 64 + c4];
        Gs[r][c4] = gv.x; Gs[r][c4 + 1] = gv.y; Gs[r][c4 + 2] = gv.z; Gs[r][c4 + 3] = gv.w;
    }
    __syncthreads();
    float acc[4][4] = {};
    #pragma unroll
    for (int d = 0; d < 64; d++) {
        float ra[4], rb[4];
        #pragma unroll
        for (int i = 0; i < 4; i++) ra[i] = Qs[ty * 4 + i][d];
        #pragma unroll
        for (int j = 0; j < 4; j++) rb[j] = Gs[d][tx * 4 + j];
        #pragma unroll
        for (int i = 0; i < 4; i++)
            #pragma unroll
            for (int j = 0; j < 4; j++) acc[i][j] = fmaf(ra[i], rb[j], acc[i][j]);
    }
    #pragma unroll
    for (int i = 0; i < 4; i++) {
        float4 o; o.x = acc[i][0]; o.y = acc[i][1]; o.z = acc[i][2]; o.w = acc[i][3];
        *(float4*)&O[(size_t)(i0 + ty * 4 + i) * DD + tx * 4] = o;
    }
}

// -------- scores = (Q' K^T)*scale, masked cols -> 0. grid (16,16,32) -------------
__global__ void __launch_bounds__(256) scores_kernel(
    const float* __restrict__ Qbase, int ldq,
    const float* __restrict__ Kbase, int ldk,
    const int* __restrict__ mask,
    float* __restrict__ S, float scale)
{
    int z = blockIdx.z; int b = z >> 4; int h = z & 15;
    const float* Q = Qbase + (size_t)b * TT * ldq + h * 64;
    const float* Kp = Kbase + (size_t)b * TT * ldk + h * 64;
    float* Sz = S + (size_t)z * TT * TT;
    __shared__ float Qs[64][65];
    __shared__ float Ks[64][65];
    int tid = threadIdx.x, tx = tid & 15, ty = tid >> 4;
    int i0 = blockIdx.y * 64, j0 = blockIdx.x * 64;
    #pragma unroll
    for (int l = 0; l < 4; l++) {
        int lin = tid + l * 256; int r = lin >> 4; int c4 = (lin & 15) * 4;
        float4 qv = *(const float4*)&Q[(size_t)(i0 + r) * ldq + c4];
        Qs[r][c4] = qv.x; Qs[r][c4 + 1] = qv.y; Qs[r][c4 + 2] = qv.z; Qs[r][c4 + 3] = qv.w;
        float4 kv = *(const float4*)&Kp[(size_t)(j0 + r) * ldk + c4];
        Ks[r][c4] = kv.x; Ks[r][c4 + 1] = kv.y; Ks[r][c4 + 2] = kv.z; Ks[r][c4 + 3] = kv.w;
    }
    __syncthreads();
    float acc[4][4] = {};
    #pragma unroll
    for (int k = 0; k < 64; k++) {
        float ra[4], rb[4];
        #pragma unroll
        for (int i = 0; i < 4; i++) ra[i] = Qs[ty * 4 + i][k];
        #pragma unroll
        for (int j = 0; j < 4; j++) rb[j] = Ks[tx * 4 + j][k];
        #pragma unroll
        for (int i = 0; i < 4; i++)
            #pragma unroll
            for (int j = 0; j < 4; j++) acc[i][j] = fmaf(ra[i], rb[j], acc[i][j]);
    }
    int cbase = j0 + tx * 4;
    float m0 = mask[b * TT + cbase + 0] ? 1.f : 0.f;
    float m1 = mask[b * TT + cbase + 1] ? 1.f : 0.f;
    float m2 = mask[b * TT + cbase + 2] ? 1.f : 0.f;
    float m3 = mask[b * TT + cbase + 3] ? 1.f : 0.f;
    #pragma unroll
    for (int i = 0; i < 4; i++) {
        int rr = i0 + ty * 4 + i;
        float4 o;
        o.x = acc[i][0] * scale * m0;
        o.y = acc[i][1] * scale * m1;
        o.z = acc[i][2] * scale * m2;
        o.w = acc[i][3] * scale * m3;
        *(float4*)&Sz[(size_t)rr * TT + cbase] = o;
    }
}

// -------- row softmax over 1024 cols, in place. grid = 32768 rows ----------------
__global__ void __launch_bounds__(256) softmax_kernel(float* __restrict__ data)
{
    __shared__ float red[8];
    size_t row = blockIdx.x;
    float4* p = (float4*)(data + row * TT);
    int tid = threadIdx.x;
    float4 v = p[tid];
    float m = fmaxf(fmaxf(v.x, v.y), fmaxf(v.z, v.w));
    #pragma unroll
    for (int o = 16; o; o >>= 1) m = fmaxf(m, __shfl_xor_sync(0xffffffffu, m, o));
    if ((tid & 31) == 0) red[tid >> 5] = m;
    __syncthreads();
    m = red[0];
    #pragma unroll
    for (int i = 1; i < 8; i++) m = fmaxf(m, red[i]);
    v.x = expf(v.x - m); v.y = expf(v.y - m); v.z = expf(v.z - m); v.w = expf(v.w - m);
    float s = v.x + v.y + v.z + v.w;
    #pragma unroll
    for (int o = 16; o; o >>= 1) s += __shfl_xor_sync(0xffffffffu, s, o);
    __syncthreads();
    if ((tid & 31) == 0) red[tid >> 5] = s;
    __syncthreads();
    s = red[0] + red[1] + red[2] + red[3] + red[4] + red[5] + red[6] + red[7];
    float inv = 1.0f / s;
    v.x *= inv; v.y *= inv; v.z *= inv; v.w *= inv;
    p[tid] = v;
}

// -------- out(merged) = att @ V per (b,h). grid (16,1,32) ------------------------
__global__ void __launch_bounds__(256) av_kernel(
    const float* __restrict__ att, const float* __restrict__ qkv, float* __restrict__ out)
{
    int z = blockIdx.z; int b = z >> 4; int h = z & 15;
    const float* Ab = att + (size_t)z * TT * TT;
    const float* V = qkv + (size_t)b * TT * A3 + 2048 + h * 64;
    float* C = out + (size_t)b * TT * DD + h * 64;
    __shared__ float As[64][65];
    __shared__ float Vs[64][65];
    int tid = threadIdx.x, tx = tid & 15, ty = tid >> 4;
    int q0 = blockIdx.x * 64;
    float acc[4][4] = {};
    for (int k0 = 0; k0 < TT; k0 += 64) {
        #pragma unroll
        for (int l = 0; l < 4; l++) {
            int lin = tid + l * 256; int r = lin >> 4; int c4 = (lin & 15) * 4;
            float4 av = *(const float4*)&Ab[(size_t)(q0 + r) * TT + k0 + c4];
            As[r][c4] = av.x; As[r][c4 + 1] = av.y; As[r][c4 + 2] = av.z; As[r][c4 + 3] = av.w;
            float4 vv = *(const float4*)&V[(size_t)(k0 + r) * A3 + c4];
            Vs[r][c4] = vv.x; Vs[r][c4 + 1] = vv.y; Vs[r][c4 + 2] = vv.z; Vs[r][c4 + 3] = vv.w;
        }
        __syncthreads();
        #pragma unroll
        for (int k = 0; k < 64; k++) {
            float ra[4], rb[4];
            #pragma unroll
            for (int i = 0; i < 4; i++) ra[i] = As[ty * 4 + i][k];
            #pragma unroll
            for (int j = 0; j < 4; j++) rb[j] = Vs[k][tx * 4 + j];
            #pragma unroll
            for (int i = 0; i < 4; i++)
                #pragma unroll
                for (int j = 0; j < 4; j++) acc[i][j] = fmaf(ra[i], rb[j], acc[i][j]);
        }
        __syncthreads();
    }
    #pragma unroll
    for (int i = 0; i < 4; i++) {
        float4 o; o.x = acc[i][0]; o.y = acc[i][1]; o.z = acc[i][2]; o.w = acc[i][3];
        *(float4*)&C[(size_t)(q0 + ty * 4 + i) * DD + tx * 4] = o;
    }
}

// -------- out = LayerNorm(x + y) * g + b.  grid = 2048 rows ----------------------
__global__ void __launch_bounds__(256) add_ln_kernel(
    const float* __restrict__ x, const float* __restrict__ y,
    const float* __restrict__ g, const float* __restrict__ beta,
    float* __restrict__ out)
{
    __shared__ float s1[8], s2[8];
    size_t row = blockIdx.x;
    int tid = threadIdx.x;
    float4 xv = ((const float4*)(x + row * DD))[tid];
    float4 yv = ((const float4*)(y + row * DD))[tid];
    float4 v;
    v.x = xv.x + yv.x; v.y = xv.y + yv.y; v.z = xv.z + yv.z; v.w = xv.w + yv.w;
    float s = v.x + v.y + v.z + v.w;
    float q = v.x * v.x + v.y * v.y + v.z * v.z + v.w * v.w;
    #pragma unroll
    for (int o = 16; o; o >>= 1) {
        s += __shfl_xor_sync(0xffffffffu, s, o);
        q += __shfl_xor_sync(0xffffffffu, q, o);
    }
    if ((tid & 31) == 0) { s1[tid >> 5] = s; s2[tid >> 5] = q; }
    __syncthreads();
    s = s1[0] + s1[1] + s1[2] + s1[3] + s1[4] + s1[5] + s1[6] + s1[7];
    q = s2[0] + s2[1] + s2[2] + s2[3] + s2[4] + s2[5] + s2[6] + s2[7];
    float mean = s * (1.0f / 1024.0f);
    float var = q * (1.0f / 1024.0f) - mean * mean;
    float r = rsqrtf(var + 1e-5f);
    float4 gv = ((const float4*)g)[tid];
    float4 bv = ((const float4*)beta)[tid];
    float4 o;
    o.x = (v.x - mean) * r * gv.x + bv.x;
    o.y = (v.y - mean) * r * gv.y + bv.y;
    o.z = (v.z - mean) * r * gv.z + bv.z;
    o.w = (v.w - mean) * r * gv.w + bv.w;
    ((float4*)(out + row * DD))[tid] = o;
}

// ----------------------------------- host ----------------------------------------
extern "C" void kernel_launch(void* const* d_in, const int* in_sizes, int n_in,
                              void* d_out, int out_size)
{
    const float* src = (const float*)d_in[0];
    const float* aux = (const float*)d_in[1];
    const float* Wu  = (const float*)d_in[2];
    const float* bu  = (const float*)d_in[3];
    const float* Wv  = (const float*)d_in[4];
    const float* bv  = (const float*)d_in[5];
    const float* Wo  = (const float*)d_in[6];
    const float* bo  = (const float*)d_in[7];
    const float* W1  = (const float*)d_in[8];
    const float* b1  = (const float*)d_in[9];
    const float* W2  = (const float*)d_in[10];
    const float* b2  = (const float*)d_in[11];
    const float* g1  = (const float*)d_in[12];
    const float* be1 = (const float*)d_in[13];
    const float* g2  = (const float*)d_in[14];
    const float* be2 = (const float*)d_in[15];
    const int* src_mask = (const int*)d_in[16];
    const int* aux_mask = (const int*)d_in[17];

    float *qkv_u, *qkv_v, *Gb, *Hb, *qp, *comb, *attn, *proj, *o1, *ffn, *f2;
    cudaGetSymbolAddress((void**)&qkv_u, g_qkv_u);
    cudaGetSymbolAddress((void**)&qkv_v, g_qkv_v);
    cudaGetSymbolAddress((void**)&Gb, g_G);
    cudaGetSymbolAddress((void**)&Hb, g_H);
    cudaGetSymbolAddress((void**)&qp, g_qp);
    cudaGetSymbolAddress((void**)&comb, g_comb);
    cudaGetSymbolAddress((void**)&attn, g_attn);
    cudaGetSymbolAddress((void**)&proj, g_proj);
    cudaGetSymbolAddress((void**)&o1, g_o1);
    cudaGetSymbolAddress((void**)&ffn, g_ffn);
    cudaGetSymbolAddress((void**)&f2, g_f2);

    const float inv64 = 1.0f / 64.0f;

    // dual-stream QKV projections
    sgemm128<<<dim3(24, 16, 1), 256>>>(src, Wu, qkv_u, 1024, 3072, 3072, 1024, 0, 0, 0, bu, 0);
    sgemm128<<<dim3(24, 16, 1), 256>>>(aux, Wv, qkv_v, 1024, 3072, 3072, 1024, 0, 0, 0, bv, 0);

    // G = K_v^T diag(aux_mask) Q_v ; H = K_u^T diag(src_mask) Q_u  (per head)
    gmat_kernel<<<32, 256>>>(qkv_v, aux_mask, Gb);
    gmat_kernel<<<32, 256>>>(qkv_u, src_mask, Hb);

    for (int s = 0; s < 2; s++) {
        const float* x   = (s == 0) ? src : aux;
        const float* qkv = (s == 0) ? qkv_u : qkv_v;
        const float* GH  = (s == 0) ? Gb : Hb;
        const int* mk    = (s == 0) ? src_mask : aux_mask;
        float* outp = (float*)d_out + (size_t)s * BT * DD;

        // comb = (Q G) K^T / 64, masked key cols -> 0   (== sim1@sim2 up to ~1e-28)
        qprime_kernel<<<dim3(16, 32), 256>>>(qkv, GH, qp);
        scores_kernel<<<dim3(16, 16, 32), 256>>>(qp, DD, qkv + 1024, A3, mk, comb, inv64);
        softmax_kernel<<<32768, 256>>>(comb);
        av_kernel<<<dim3(16, 1, 32), 256>>>(comb, qkv, attn);

        // output projection + LN + FFN + LN
        sgemm128<<<dim3(8, 16, 1), 256>>>(attn, Wo, proj, 1024, 1024, 1024, 1024, 0, 0, 0, bo, 0);
        add_ln_kernel<<<2048, 256>>>(x, proj, g1, be1, o1);
        sgemm128<<<dim3(32, 16, 1), 256>>>(o1, W1, ffn, 1024, 4096, 4096, 1024, 0, 0, 0, b1, 1);
        sgemm128<<<dim3(8, 16, 1), 256>>>(ffn, W2, f2, 4096, 1024, 1024, 4096, 0, 0, 0, b2, 0);
        add_ln_kernel<<<2048, 256>>>(o1, f2, g2, be2, outp);
    }
}

// round 5
// speedup vs baseline: 2.0053x; 2.0053x over previous
#include <cuda_runtime.h>

#define TT 1024      // timesteps
#define DD 1024      // model dim
#define A3 3072      // 3 * attention_dim
#define FF 4096      // feedforward dim
#define BT 2048      // B * T rows
#define NBH 32       // B * H batched heads

// ---------------- scratch (device globals; no allocations allowed) ----------------
__device__ float g_qkv_u[BT * A3];
__device__ float g_qkv_v[BT * A3];
__device__ float g_G[NBH * 4096];
__device__ float g_H[NBH * 4096];
__device__ float g_Gpart[8 * NBH * 4096];
__device__ float g_qp[BT * DD];
__device__ float g_comb[(size_t)NBH * TT * TT];
__device__ float g_attn[BT * DD];
__device__ float g_proj[BT * DD];
__device__ float g_o1[BT * DD];
__device__ float g_ffn[BT * FF];
__device__ float g_f2[BT * DD];

// xor-swizzled smem offset: row k (16 rows), m within row of width W.
// swizzle uses k bits [0:1]^[2:3] so BOTH the transpose-stores (k varies by
// 4*(lane&3)+s) and the fragment loads (k varies by lane&3) hit 32 distinct banks.
#define SWZ(k, m, W) (((k) * (W)) + ((m) ^ (((((k) & 3) ^ (((k) >> 2) & 3))) << 3)))

__device__ __forceinline__ unsigned f2tf32(float x) {
    unsigned r;
    asm("cvt.rna.tf32.f32 %0, %1;" : "=r"(r) : "f"(x));
    return r;
}

#define MMA_TF32(d, a, b)                                                      \
    asm volatile(                                                              \
        "mma.sync.aligned.m16n8k8.row.col.f32.tf32.tf32.f32 "                  \
        "{%0,%1,%2,%3},{%4,%5,%6,%7},{%8,%9},{%0,%1,%2,%3};"                   \
        : "+f"((d)[0]), "+f"((d)[1]), "+f"((d)[2]), "+f"((d)[3])               \
        : "r"((a)[0]), "r"((a)[1]), "r"((a)[2]), "r"((a)[3]),                  \
          "r"((b)[0]), "r"((b)[1]))

// ---------------------------------------------------------------------------------
// Tensor-core GEMM: C[M x N] = A[M x K] * B (+bias, relu, scale, col-mask)
// BN: 128 or 64 (block tile N). PREC: 1 = tf32, 3 = 3xTF32 (fp32-accurate).
// Batched via blockIdx.z with (b = z>>4, h = z&15) strides.
// transB = 0: B is [K][N] row-major; transB = 1: B is [N][K] (computes A*B^T).
// ---------------------------------------------------------------------------------
template <int BN, int PREC>
__global__ void __launch_bounds__(256) mma_gemm(
    const float* __restrict__ A, int lda, long long sAb, long long sAh,
    const float* __restrict__ B, int ldb, long long sBb, long long sBh, int transB,
    float* __restrict__ C, int ldc, long long sCb, long long sCh,
    int K, const float* __restrict__ bias, int relu, float scale,
    const int* __restrict__ mask)
{
    constexpr int NF = BN / 16;                 // n-fragments per warp (warp tile N = BN/2)
    constexpr int BF4 = (BN * 16 / 4) / 256;    // float4 loads per thread for B tile

    __shared__ float As[2][16 * 128];
    __shared__ float Bs[2][16 * BN];

    int z = blockIdx.z, b = z >> 4, h = z & 15;
    A += (size_t)b * sAb + (size_t)h * sAh;
    B += (size_t)b * sBb + (size_t)h * sBh;
    C += (size_t)b * sCb + (size_t)h * sCh;
    const int* mrow = mask ? (mask + b * TT) : (const int*)0;

    int tid = threadIdx.x, lane = tid & 31, warp = tid >> 5;
    int wy = warp >> 1, wx = warp & 1;
    int wm = wy * 32, wn = wx * (BN / 2);
    int g = lane >> 2, q = lane & 3;
    int m0 = blockIdx.y * 128, n0 = blockIdx.x * BN;

    float acc[2][NF][4];
    #pragma unroll
    for (int mi = 0; mi < 2; mi++)
        #pragma unroll
        for (int nj = 0; nj < NF; nj++)
            #pragma unroll
            for (int e = 0; e < 4; e++) acc[mi][nj][e] = 0.f;

    float4 va[2];
    float4 vb[BF4];

    auto loadA = [&](int k0) {
        #pragma unroll
        for (int i = 0; i < 2; i++) {
            int id = tid + 256 * i;
            int r = id >> 2, c4 = (id & 3) * 4;
            va[i] = *(const float4*)&A[(size_t)(m0 + r) * lda + k0 + c4];
        }
    };
    auto storeA = [&](int bf) {
        float* p = &As[bf][0];
        #pragma unroll
        for (int i = 0; i < 2; i++) {
            int id = tid + 256 * i;
            int r = id >> 2, c4 = (id & 3) * 4;
            p[SWZ(c4 + 0, r, 128)] = va[i].x;
            p[SWZ(c4 + 1, r, 128)] = va[i].y;
            p[SWZ(c4 + 2, r, 128)] = va[i].z;
            p[SWZ(c4 + 3, r, 128)] = va[i].w;
        }
    };
    auto loadB = [&](int k0) {
        if (!transB) {
            #pragma unroll
            for (int i = 0; i < BF4; i++) {
                int id = tid + 256 * i;
                int kr = id / (BN / 4), nc4 = (id % (BN / 4)) * 4;
                vb[i] = *(const float4*)&B[(size_t)(k0 + kr) * ldb + n0 + nc4];
            }
        } else {
            #pragma unroll
            for (int i = 0; i < BF4; i++) {
                int id = tid + 256 * i;
                int n = id >> 2, c4 = (id & 3) * 4;
                vb[i] = *(const float4*)&B[(size_t)(n0 + n) * ldb + k0 + c4];
            }
        }
    };
    auto storeB = [&](int bf) {
        float* p = &Bs[bf][0];
        if (!transB) {
            #pragma unroll
            for (int i = 0; i < BF4; i++) {
                int id = tid + 256 * i;
                int kr = id / (BN / 4), nc4 = (id % (BN / 4)) * 4;
                int sw = (((kr & 3) ^ ((kr >> 2) & 3)) << 3);
                *(float4*)&p[kr * BN + (nc4 ^ sw)] = vb[i];
            }
        } else {
            #pragma unroll
            for (int i = 0; i < BF4; i++) {
                int id = tid + 256 * i;
                int n = id >> 2, c4 = (id & 3) * 4;
                p[SWZ(c4 + 0, n, BN)] = vb[i].x;
                p[SWZ(c4 + 1, n, BN)] = vb[i].y;
                p[SWZ(c4 + 2, n, BN)] = vb[i].z;
                p[SWZ(c4 + 3, n, BN)] = vb[i].w;
            }
        }
    };

    loadA(0); loadB(0);
    storeA(0); storeB(0);
    __syncthreads();

    int buf = 0;
    for (int k0 = 0; k0 < K; k0 += 16) {
        bool more = (k0 + 16) < K;
        if (more) { loadA(k0 + 16); loadB(k0 + 16); }

        #pragma unroll
        for (int kk = 0; kk < 16; kk += 8) {
            unsigned ah[2][4], bh[NF][2];
            unsigned al[2][4], bl[NF][2];
            #pragma unroll
            for (int mi = 0; mi < 2; mi++) {
                #pragma unroll
                for (int e = 0; e < 4; e++) {
                    int kq = kk + q + ((e >= 2) ? 4 : 0);
                    int m = wm + mi * 16 + g + ((e & 1) ? 8 : 0);
                    float x = As[buf][SWZ(kq, m, 128)];
                    ah[mi][e] = f2tf32(x);
                    if (PREC == 3)
                        al[mi][e] = f2tf32(x - __uint_as_float(ah[mi][e]));
                }
            }
            #pragma unroll
            for (int nj = 0; nj < NF; nj++) {
                int n = wn + nj * 8 + g;
                float x0 = Bs[buf][SWZ(kk + q, n, BN)];
                float x1 = Bs[buf][SWZ(kk + q + 4, n, BN)];
                bh[nj][0] = f2tf32(x0);
                bh[nj][1] = f2tf32(x1);
                if (PREC == 3) {
                    bl[nj][0] = f2tf32(x0 - __uint_as_float(bh[nj][0]));
                    bl[nj][1] = f2tf32(x1 - __uint_as_float(bh[nj][1]));
                }
            }
            #pragma unroll
            for (int mi = 0; mi < 2; mi++)
                #pragma unroll
                for (int nj = 0; nj < NF; nj++) {
                    MMA_TF32(acc[mi][nj], ah[mi], bh[nj]);
                    if (PREC == 3) {
                        MMA_TF32(acc[mi][nj], ah[mi], bl[nj]);
                        MMA_TF32(acc[mi][nj], al[mi], bh[nj]);
                    }
                }
        }

        if (more) {
            storeA(buf ^ 1); storeB(buf ^ 1);
            buf ^= 1;
            __syncthreads();
        }
    }

    // epilogue
    #pragma unroll
    for (int mi = 0; mi < 2; mi++)
        #pragma unroll
        for (int r2 = 0; r2 < 2; r2++) {
            int row = m0 + wm + mi * 16 + g + r2 * 8;
            #pragma unroll
            for (int nj = 0; nj < NF; nj++) {
                int col = n0 + wn + nj * 8 + 2 * q;
                float v0 = acc[mi][nj][r2 * 2 + 0] * scale;
                float v1 = acc[mi][nj][r2 * 2 + 1] * scale;
                if (bias) { v0 += bias[col]; v1 += bias[col + 1]; }
                if (mrow) {
                    if (!mrow[col]) v0 = 0.f;
                    if (!mrow[col + 1]) v1 = 0.f;
                }
                if (relu) { v0 = fmaxf(v0, 0.f); v1 = fmaxf(v1, 0.f); }
                float2 o; o.x = v0; o.y = v1;
                *(float2*)&C[(size_t)row * ldc + col] = o;
            }
        }
}

// -------- split-K G partials: G = K^T diag(mask) Q per (b,h). grid (32, 8) -------
__global__ void __launch_bounds__(256) gmat_part(
    const float* __restrict__ qkv, const int* __restrict__ mask, float* __restrict__ part)
{
    int z = blockIdx.x; int b = z >> 4; int h = z & 15;
    int tb = blockIdx.y * 128;
    const float* Kb = qkv + (size_t)b * TT * A3 + 1024 + h * 64;
    const float* Qb = qkv + (size_t)b * TT * A3 + h * 64;
    __shared__ float Ks[64][65];
    __shared__ float Qs[64][65];
    int tid = threadIdx.x, tx = tid & 15, ty = tid >> 4;
    float acc[4][4] = {};

    for (int t0 = tb; t0 < tb + 128; t0 += 64) {
        #pragma unroll
        for (int l = 0; l < 4; l++) {
            int lin = tid + l * 256; int r = lin >> 4; int c4 = (lin & 15) * 4;
            int trow = t0 + r;
            float mk = mask[b * TT + trow] ? 1.0f : 0.0f;
            float4 kv = *(const float4*)&Kb[(size_t)trow * A3 + c4];
            Ks[r][c4] = kv.x * mk; Ks[r][c4 + 1] = kv.y * mk;
            Ks[r][c4 + 2] = kv.z * mk; Ks[r][c4 + 3] = kv.w * mk;
            float4 qv = *(const float4*)&Qb[(size_t)trow * A3 + c4];
            Qs[r][c4] = qv.x; Qs[r][c4 + 1] = qv.y; Qs[r][c4 + 2] = qv.z; Qs[r][c4 + 3] = qv.w;
        }
        __syncthreads();
        #pragma unroll
        for (int t = 0; t < 64; t++) {
            float ra[4], rb[4];
            #pragma unroll
            for (int i = 0; i < 4; i++) ra[i] = Ks[t][ty * 4 + i];
            #pragma unroll
            for (int j = 0; j < 4; j++) rb[j] = Qs[t][tx * 4 + j];
            #pragma unroll
            for (int i = 0; i < 4; i++)
                #pragma unroll
                for (int j = 0; j < 4; j++) acc[i][j] = fmaf(ra[i], rb[j], acc[i][j]);
        }
        __syncthreads();
    }
    float* P = part + ((size_t)blockIdx.y * NBH + z) * 4096;
    #pragma unroll
    for (int i = 0; i < 4; i++) {
        float4 o; o.x = acc[i][0]; o.y = acc[i][1]; o.z = acc[i][2]; o.w = acc[i][3];
        *(float4*)&P[(ty * 4 + i) * 64 + tx * 4] = o;
    }
}

__global__ void __launch_bounds__(256) gmat_reduce(
    const float* __restrict__ part, float* __restrict__ G)
{
    int z = blockIdx.x;
    for (int e = threadIdx.x; e < 4096; e += 256) {
        float s = 0.f;
        #pragma unroll
        for (int k = 0; k < 8; k++) s += part[((size_t)k * NBH + z) * 4096 + e];
        G[(size_t)z * 4096 + e] = s;
    }
}

// -------- row softmax over 1024 cols, in place. grid = 32768 rows ----------------
__global__ void __launch_bounds__(256) softmax_kernel(float* __restrict__ data)
{
    __shared__ float red[8];
    size_t row = blockIdx.x;
    float4* p = (float4*)(data + row * TT);
    int tid = threadIdx.x;
    float4 v = p[tid];
    float m = fmaxf(fmaxf(v.x, v.y), fmaxf(v.z, v.w));
    #pragma unroll
    for (int o = 16; o; o >>= 1) m = fmaxf(m, __shfl_xor_sync(0xffffffffu, m, o));
    if ((tid & 31) == 0) red[tid >> 5] = m;
    __syncthreads();
    m = red[0];
    #pragma unroll
    for (int i = 1; i < 8; i++) m = fmaxf(m, red[i]);
    v.x = expf(v.x - m); v.y = expf(v.y - m); v.z = expf(v.z - m); v.w = expf(v.w - m);
    float s = v.x + v.y + v.z + v.w;
    #pragma unroll
    for (int o = 16; o; o >>= 1) s += __shfl_xor_sync(0xffffffffu, s, o);
    __syncthreads();
    if ((tid & 31) == 0) red[tid >> 5] = s;
    __syncthreads();
    s = red[0] + red[1] + red[2] + red[3] + red[4] + red[5] + red[6] + red[7];
    float inv = 1.0f / s;
    v.x *= inv; v.y *= inv; v.z *= inv; v.w *= inv;
    p[tid] = v;
}

// -------- out = LayerNorm(x + y) * g + b.  grid = 2048 rows ----------------------
__global__ void __launch_bounds__(256) add_ln_kernel(
    const float* __restrict__ x, const float* __restrict__ y,
    const float* __restrict__ g, const float* __restrict__ beta,
    float* __restrict__ out)
{
    __shared__ float s1[8], s2[8];
    size_t row = blockIdx.x;
    int tid = threadIdx.x;
    float4 xv = ((const float4*)(x + row * DD))[tid];
    float4 yv = ((const float4*)(y + row * DD))[tid];
    float4 v;
    v.x = xv.x + yv.x; v.y = xv.y + yv.y; v.z = xv.z + yv.z; v.w = xv.w + yv.w;
    float s = v.x + v.y + v.z + v.w;
    float q = v.x * v.x + v.y * v.y + v.z * v.z + v.w * v.w;
    #pragma unroll
    for (int o = 16; o; o >>= 1) {
        s += __shfl_xor_sync(0xffffffffu, s, o);
        q += __shfl_xor_sync(0xffffffffu, q, o);
    }
    if ((tid & 31) == 0) { s1[tid >> 5] = s; s2[tid >> 5] = q; }
    __syncthreads();
    s = s1[0] + s1[1] + s1[2] + s1[3] + s1[4] + s1[5] + s1[6] + s1[7];
    q = s2[0] + s2[1] + s2[2] + s2[3] + s2[4] + s2[5] + s2[6] + s2[7];
    float mean = s * (1.0f / 1024.0f);
    float var = q * (1.0f / 1024.0f) - mean * mean;
    float r = rsqrtf(var + 1e-5f);
    float4 gv = ((const float4*)g)[tid];
    float4 bv = ((const float4*)beta)[tid];
    float4 o;
    o.x = (v.x - mean) * r * gv.x + bv.x;
    o.y = (v.y - mean) * r * gv.y + bv.y;
    o.z = (v.z - mean) * r * gv.z + bv.z;
    o.w = (v.w - mean) * r * gv.w + bv.w;
    ((float4*)(out + row * DD))[tid] = o;
}

// ----------------------------------- host ----------------------------------------
extern "C" void kernel_launch(void* const* d_in, const int* in_sizes, int n_in,
                              void* d_out, int out_size)
{
    const float* src = (const float*)d_in[0];
    const float* aux = (const float*)d_in[1];
    const float* Wu  = (const float*)d_in[2];
    const float* bu  = (const float*)d_in[3];
    const float* Wv  = (const float*)d_in[4];
    const float* bv  = (const float*)d_in[5];
    const float* Wo  = (const float*)d_in[6];
    const float* bo  = (const float*)d_in[7];
    const float* W1  = (const float*)d_in[8];
    const float* b1  = (const float*)d_in[9];
    const float* W2  = (const float*)d_in[10];
    const float* b2  = (const float*)d_in[11];
    const float* g1  = (const float*)d_in[12];
    const float* be1 = (const float*)d_in[13];
    const float* g2  = (const float*)d_in[14];
    const float* be2 = (const float*)d_in[15];
    const int* src_mask = (const int*)d_in[16];
    const int* aux_mask = (const int*)d_in[17];

    float *qkv_u, *qkv_v, *Gb, *Hb, *Gpart, *qp, *comb, *attn, *proj, *o1, *ffn, *f2;
    cudaGetSymbolAddress((void**)&qkv_u, g_qkv_u);
    cudaGetSymbolAddress((void**)&qkv_v, g_qkv_v);
    cudaGetSymbolAddress((void**)&Gb, g_G);
    cudaGetSymbolAddress((void**)&Hb, g_H);
    cudaGetSymbolAddress((void**)&Gpart, g_Gpart);
    cudaGetSymbolAddress((void**)&qp, g_qp);
    cudaGetSymbolAddress((void**)&comb, g_comb);
    cudaGetSymbolAddress((void**)&attn, g_attn);
    cudaGetSymbolAddress((void**)&proj, g_proj);
    cudaGetSymbolAddress((void**)&o1, g_o1);
    cudaGetSymbolAddress((void**)&ffn, g_ffn);
    cudaGetSymbolAddress((void**)&f2, g_f2);

    const float inv64 = 1.0f / 64.0f;
    const long long Z = 0;

    // dual-stream QKV projections (3xTF32: feeds the logit chain)
    mma_gemm<128, 3><<<dim3(24, 16, 1), 256>>>(src, 1024, Z, Z, Wu, 3072, Z, Z, 0,
                                               qkv_u, 3072, Z, Z, 1024, bu, 0, 1.f, (const int*)0);
    mma_gemm<128, 3><<<dim3(24, 16, 1), 256>>>(aux, 1024, Z, Z, Wv, 3072, Z, Z, 0,
                                               qkv_v, 3072, Z, Z, 1024, bv, 0, 1.f, (const int*)0);

    // G = K_v^T diag(aux_mask) Q_v ; H = K_u^T diag(src_mask) Q_u  (split-K + reduce)
    gmat_part<<<dim3(32, 8), 256>>>(qkv_v, aux_mask, Gpart);
    gmat_reduce<<<32, 256>>>(Gpart, Gb);
    gmat_part<<<dim3(32, 8), 256>>>(qkv_u, src_mask, Gpart);
    gmat_reduce<<<32, 256>>>(Gpart, Hb);

    for (int s = 0; s < 2; s++) {
        const float* x   = (s == 0) ? src : aux;
        const float* qkv = (s == 0) ? qkv_u : qkv_v;
        const float* GH  = (s == 0) ? Gb : Hb;
        const int* mk    = (s == 0) ? src_mask : aux_mask;
        float* outp = (float*)d_out + (size_t)s * BT * DD;

        // Q' = Q @ G   (3xTF32, batched per head, N=64)
        mma_gemm<64, 3><<<dim3(1, 8, 32), 256>>>(
            qkv, A3, (long long)TT * A3, 64,
            GH, 64, (long long)16 * 4096, 4096, 0,
            qp, DD, (long long)TT * DD, 64,
            64, (const float*)0, 0, 1.f, (const int*)0);

        // comb = (Q' K^T)/64, masked key cols -> 0  (3xTF32, A*B^T)
        mma_gemm<128, 3><<<dim3(8, 8, 32), 256>>>(
            qp, DD, (long long)TT * DD, 64,
            qkv + 1024, A3, (long long)TT * A3, 64, 1,
            comb, TT, (long long)16 * TT * TT, (long long)TT * TT,
            64, (const float*)0, 0, inv64, mk);

        softmax_kernel<<<32768, 256>>>(comb);

        // attn = att @ V  (tf32, batched per head, N=64)
        mma_gemm<64, 1><<<dim3(1, 8, 32), 256>>>(
            comb, TT, (long long)16 * TT * TT, (long long)TT * TT,
            qkv + 2048, A3, (long long)TT * A3, 64, 0,
            attn, DD, (long long)TT * DD, 64,
            TT, (const float*)0, 0, 1.f, (const int*)0);

        // output projection + LN + FFN + LN  (tf32)
        mma_gemm<128, 1><<<dim3(8, 16, 1), 256>>>(attn, 1024, Z, Z, Wo, 1024, Z, Z, 0,
                                                  proj, 1024, Z, Z, 1024, bo, 0, 1.f, (const int*)0);
        add_ln_kernel<<<2048, 256>>>(x, proj, g1, be1, o1);
        mma_gemm<128, 1><<<dim3(32, 16, 1), 256>>>(o1, 1024, Z, Z, W1, 4096, Z, Z, 0,
                                                   ffn, 4096, Z, Z, 1024, b1, 1, 1.f, (const int*)0);
        mma_gemm<128, 1><<<dim3(8, 16, 1), 256>>>(ffn, 4096, Z, Z, W2, 1024, Z, Z, 0,
                                                  f2, 1024, Z, Z, 4096, b2, 0, 1.f, (const int*)0);
        add_ln_kernel<<<2048, 256>>>(o1, f2, g2, be2, outp);
    }
}

// round 10
// speedup vs baseline: 2.2484x; 1.1212x over previous
#include <cuda_runtime.h>

#define TT 1024      // timesteps
#define DD 1024      // model dim
#define A3 3072      // 3 * attention_dim
#define FF 4096      // feedforward dim
#define BT 2048      // B * T rows
#define NBH 32       // B * H batched heads

// ---------------- scratch (device globals; no allocations allowed) ----------------
__device__ float g_qkv_u[BT * A3];
__device__ float g_qkv_v[BT * A3];
__device__ float g_G[NBH * 4096];
__device__ float g_H[NBH * 4096];
__device__ float g_Gpart[8 * NBH * 4096];
__device__ float g_qp[BT * DD];
__device__ float g_comb[(size_t)NBH * TT * TT];
__device__ float g_attn[BT * DD];
__device__ float g_proj[BT * DD];
__device__ float g_o1[BT * DD];
__device__ float g_ffn[BT * FF];
__device__ float g_f2[BT * DD];

// xor-swizzled smem offset: row k (16 rows), m within row of width W.
#define SWZ(k, m, W) (((k) * (W)) + ((m) ^ (((((k) & 3) ^ (((k) >> 2) & 3))) << 3)))

__device__ __forceinline__ float f2tf32f(float x) {
    unsigned r;
    asm("cvt.rna.tf32.f32 %0, %1;" : "=r"(r) : "f"(x));
    return __uint_as_float(r);
}

#define MMA_TF32(d, a, b)                                                      \
    asm volatile(                                                              \
        "mma.sync.aligned.m16n8k8.row.col.f32.tf32.tf32.f32 "                  \
        "{%0,%1,%2,%3},{%4,%5,%6,%7},{%8,%9},{%0,%1,%2,%3};"                   \
        : "+f"((d)[0]), "+f"((d)[1]), "+f"((d)[2]), "+f"((d)[3])               \
        : "r"((a)[0]), "r"((a)[1]), "r"((a)[2]), "r"((a)[3]),                  \
          "r"((b)[0]), "r"((b)[1]))

// ---------------------------------------------------------------------------------
// Tensor-core GEMM: C[M x N] = A[M x K] * B (+bias, relu, scale, col-mask)
// BN: 128 or 64. PREC: 1 = tf32, 3 = 3xTF32 (fp32-accurate).
// tf32 conversion (hi + lo residual) happens ONCE at smem-store time; the inner
// loop is pure LDS + HMMA.
// ---------------------------------------------------------------------------------
template <int BN, int PREC>
__global__ void __launch_bounds__(256) mma_gemm(
    const float* __restrict__ A, int lda, long long sAb, long long sAh,
    const float* __restrict__ B, int ldb, long long sBb, long long sBh, int transB,
    float* __restrict__ C, int ldc, long long sCb, long long sCh,
    int K, const float* __restrict__ bias, int relu, float scale,
    const int* __restrict__ mask)
{
    constexpr int NF = BN / 16;                 // n-fragments per warp
    constexpr int BF4 = (BN * 16 / 4) / 256;    // float4 loads per thread for B tile
    constexpr int CC = (PREC == 3) ? 2 : 1;     // components (hi, lo)
    constexpr int AE = 16 * 128;                // elems per A buffer component
    constexpr int BE = 16 * BN;
    constexpr int NH = (NF > 4) ? 2 : 1;        // n-fragment halves
    constexpr int NFH = NF / NH;

    extern __shared__ float sm[];
    float* Asm = sm;                    // [2][CC*AE]
    float* Bsm = sm + 2 * CC * AE;      // [2][CC*BE]

    int z = blockIdx.z, b = z >> 4, h = z & 15;
    A += (size_t)b * sAb + (size_t)h * sAh;
    B += (size_t)b * sBb + (size_t)h * sBh;
    C += (size_t)b * sCb + (size_t)h * sCh;
    const int* mrow = mask ? (mask + b * TT) : (const int*)0;

    int tid = threadIdx.x, lane = tid & 31, warp = tid >> 5;
    int wy = warp >> 1, wx = warp & 1;
    int wm = wy * 32, wn = wx * (BN / 2);
    int g = lane >> 2, q = lane & 3;
    int m0 = blockIdx.y * 128, n0 = blockIdx.x * BN;

    float acc[2][NF][4];
    #pragma unroll
    for (int mi = 0; mi < 2; mi++)
        #pragma unroll
        for (int nj = 0; nj < NF; nj++)
            #pragma unroll
            for (int e = 0; e < 4; e++) acc[mi][nj][e] = 0.f;

    float4 va[2];
    float4 vb[BF4];

    auto loadA = [&](int k0) {
        #pragma unroll
        for (int i = 0; i < 2; i++) {
            int id = tid + 256 * i;
            int r = id >> 2, c4 = (id & 3) * 4;
            va[i] = *(const float4*)&A[(size_t)(m0 + r) * lda + k0 + c4];
        }
    };
    auto storeA = [&](int bf) {
        float* p = Asm + bf * CC * AE;
        #pragma unroll
        for (int i = 0; i < 2; i++) {
            int id = tid + 256 * i;
            int r = id >> 2, c4 = (id & 3) * 4;
            float xs[4] = {va[i].x, va[i].y, va[i].z, va[i].w};
            #pragma unroll
            for (int s = 0; s < 4; s++) {
                float hi = f2tf32f(xs[s]);
                p[SWZ(c4 + s, r, 128)] = hi;
                if (PREC == 3) p[AE + SWZ(c4 + s, r, 128)] = f2tf32f(xs[s] - hi);
            }
        }
    };
    auto loadB = [&](int k0) {
        if (!transB) {
            #pragma unroll
            for (int i = 0; i < BF4; i++) {
                int id = tid + 256 * i;
                int kr = id / (BN / 4), nc4 = (id % (BN / 4)) * 4;
                vb[i] = *(const float4*)&B[(size_t)(k0 + kr) * ldb + n0 + nc4];
            }
        } else {
            #pragma unroll
            for (int i = 0; i < BF4; i++) {
                int id = tid + 256 * i;
                int n = id >> 2, c4 = (id & 3) * 4;
                vb[i] = *(const float4*)&B[(size_t)(n0 + n) * ldb + k0 + c4];
            }
        }
    };
    auto storeB = [&](int bf) {
        float* p = Bsm + bf * CC * BE;
        if (!transB) {
            #pragma unroll
            for (int i = 0; i < BF4; i++) {
                int id = tid + 256 * i;
                int kr = id / (BN / 4), nc4 = (id % (BN / 4)) * 4;
                int sw = (((kr & 3) ^ ((kr >> 2) & 3)) << 3);
                float xs[4] = {vb[i].x, vb[i].y, vb[i].z, vb[i].w};
                float4 hv, lv;
                hv.x = f2tf32f(xs[0]); hv.y = f2tf32f(xs[1]);
                hv.z = f2tf32f(xs[2]); hv.w = f2tf32f(xs[3]);
                *(float4*)&p[kr * BN + (nc4 ^ sw)] = hv;
                if (PREC == 3) {
                    lv.x = f2tf32f(xs[0] - hv.x); lv.y = f2tf32f(xs[1] - hv.y);
                    lv.z = f2tf32f(xs[2] - hv.z); lv.w = f2tf32f(xs[3] - hv.w);
                    *(float4*)&p[BE + kr * BN + (nc4 ^ sw)] = lv;
                }
            }
        } else {
            #pragma unroll
            for (int i = 0; i < BF4; i++) {
                int id = tid + 256 * i;
                int n = id >> 2, c4 = (id & 3) * 4;
                float xs[4] = {vb[i].x, vb[i].y, vb[i].z, vb[i].w};
                #pragma unroll
                for (int s = 0; s < 4; s++) {
                    float hi = f2tf32f(xs[s]);
                    p[SWZ(c4 + s, n, BN)] = hi;
                    if (PREC == 3) p[BE + SWZ(c4 + s, n, BN)] = f2tf32f(xs[s] - hi);
                }
            }
        }
    };

    loadA(0); loadB(0);
    storeA(0); storeB(0);
    __syncthreads();

    int buf = 0;
    for (int k0 = 0; k0 < K; k0 += 16) {
        bool more = (k0 + 16) < K;
        if (more) { loadA(k0 + 16); loadB(k0 + 16); }

        const float* pa = Asm + buf * CC * AE;
        const float* pb = Bsm + buf * CC * BE;

        #pragma unroll
        for (int kk = 0; kk < 16; kk += 8) {
            unsigned ah[2][4], al[2][4];
            #pragma unroll
            for (int mi = 0; mi < 2; mi++) {
                #pragma unroll
                for (int e = 0; e < 4; e++) {
                    int kq = kk + q + ((e >= 2) ? 4 : 0);
                    int m = wm + mi * 16 + g + ((e & 1) ? 8 : 0);
                    ah[mi][e] = __float_as_uint(pa[SWZ(kq, m, 128)]);
                    if (PREC == 3) al[mi][e] = __float_as_uint(pa[AE + SWZ(kq, m, 128)]);
                }
            }
            #pragma unroll
            for (int hh = 0; hh < NH; hh++) {
                unsigned bh[NFH][2], bl[NFH][2];
                #pragma unroll
                for (int j = 0; j < NFH; j++) {
                    int n = wn + (hh * NFH + j) * 8 + g;
                    bh[j][0] = __float_as_uint(pb[SWZ(kk + q, n, BN)]);
                    bh[j][1] = __float_as_uint(pb[SWZ(kk + q + 4, n, BN)]);
                    if (PREC == 3) {
                        bl[j][0] = __float_as_uint(pb[BE + SWZ(kk + q, n, BN)]);
                        bl[j][1] = __float_as_uint(pb[BE + SWZ(kk + q + 4, n, BN)]);
                    }
                }
                #pragma unroll
                for (int mi = 0; mi < 2; mi++)
                    #pragma unroll
                    for (int j = 0; j < NFH; j++) {
                        int nj = hh * NFH + j;
                        MMA_TF32(acc[mi][nj], ah[mi], bh[j]);
                        if (PREC == 3) {
                            MMA_TF32(acc[mi][nj], ah[mi], bl[j]);
                            MMA_TF32(acc[mi][nj], al[mi], bh[j]);
                        }
                    }
            }
        }

        if (more) {
            storeA(buf ^ 1); storeB(buf ^ 1);
            buf ^= 1;
            __syncthreads();
        }
    }

    // epilogue
    #pragma unroll
    for (int mi = 0; mi < 2; mi++)
        #pragma unroll
        for (int r2 = 0; r2 < 2; r2++) {
            int row = m0 + wm + mi * 16 + g + r2 * 8;
            #pragma unroll
            for (int nj = 0; nj < NF; nj++) {
                int col = n0 + wn + nj * 8 + 2 * q;
                float v0 = acc[mi][nj][r2 * 2 + 0] * scale;
                float v1 = acc[mi][nj][r2 * 2 + 1] * scale;
                if (bias) { v0 += bias[col]; v1 += bias[col + 1]; }
                if (mrow) {
                    if (!mrow[col]) v0 = 0.f;
                    if (!mrow[col + 1]) v1 = 0.f;
                }
                if (relu) { v0 = fmaxf(v0, 0.f); v1 = fmaxf(v1, 0.f); }
                float2 o; o.x = v0; o.y = v1;
                *(float2*)&C[(size_t)row * ldc + col] = o;
            }
        }
}

// -------- split-K G partials: G = K^T diag(mask) Q per (b,h). grid (32, 8) -------
__global__ void __launch_bounds__(256) gmat_part(
    const float* __restrict__ qkv, const int* __restrict__ mask, float* __restrict__ part)
{
    int z = blockIdx.x; int b = z >> 4; int h = z & 15;
    int tb = blockIdx.y * 128;
    const float* Kb = qkv + (size_t)b * TT * A3 + 1024 + h * 64;
    const float* Qb = qkv + (size_t)b * TT * A3 + h * 64;
    __shared__ float Ks[64][65];
    __shared__ float Qs[64][65];
    int tid = threadIdx.x, tx = tid & 15, ty = tid >> 4;
    float acc[4][4] = {};

    for (int t0 = tb; t0 < tb + 128; t0 += 64) {
        #pragma unroll
        for (int l = 0; l < 4; l++) {
            int lin = tid + l * 256; int r = lin >> 4; int c4 = (lin & 15) * 4;
            int trow = t0 + r;
            float mk = mask[b * TT + trow] ? 1.0f : 0.0f;
            float4 kv = *(const float4*)&Kb[(size_t)trow * A3 + c4];
            Ks[r][c4] = kv.x * mk; Ks[r][c4 + 1] = kv.y * mk;
            Ks[r][c4 + 2] = kv.z * mk; Ks[r][c4 + 3] = kv.w * mk;
            float4 qv = *(const float4*)&Qb[(size_t)trow * A3 + c4];
            Qs[r][c4] = qv.x; Qs[r][c4 + 1] = qv.y; Qs[r][c4 + 2] = qv.z; Qs[r][c4 + 3] = qv.w;
        }
        __syncthreads();
        #pragma unroll
        for (int t = 0; t < 64; t++) {
            float ra[4], rb[4];
            #pragma unroll
            for (int i = 0; i < 4; i++) ra[i] = Ks[t][ty * 4 + i];
            #pragma unroll
            for (int j = 0; j < 4; j++) rb[j] = Qs[t][tx * 4 + j];
            #pragma unroll
            for (int i = 0; i < 4; i++)
                #pragma unroll
                for (int j = 0; j < 4; j++) acc[i][j] = fmaf(ra[i], rb[j], acc[i][j]);
        }
        __syncthreads();
    }
    float* P = part + ((size_t)blockIdx.y * NBH + z) * 4096;
    #pragma unroll
    for (int i = 0; i < 4; i++) {
        float4 o; o.x = acc[i][0]; o.y = acc[i][1]; o.z = acc[i][2]; o.w = acc[i][3];
        *(float4*)&P[(ty * 4 + i) * 64 + tx * 4] = o;
    }
}

// grid (32, 8): each block reduces 512 elements of one head's 64x64 G
__global__ void __launch_bounds__(256) gmat_reduce(
    const float* __restrict__ part, float* __restrict__ G)
{
    int z = blockIdx.x;
    int e = blockIdx.y * 512 + threadIdx.x;
    #pragma unroll
    for (int i = 0; i < 2; i++, e += 256) {
        float s = 0.f;
        #pragma unroll
        for (int k = 0; k < 8; k++) s += part[((size_t)k * NBH + z) * 4096 + e];
        G[(size_t)z * 4096 + e] = s;
    }
}

// -------- row softmax over 1024 cols, in place. grid = 32768 rows ----------------
__global__ void __launch_bounds__(256) softmax_kernel(float* __restrict__ data)
{
    __shared__ float red[8];
    size_t row = blockIdx.x;
    float4* p = (float4*)(data + row * TT);
    int tid = threadIdx.x;
    float4 v = p[tid];
    float m = fmaxf(fmaxf(v.x, v.y), fmaxf(v.z, v.w));
    #pragma unroll
    for (int o = 16; o; o >>= 1) m = fmaxf(m, __shfl_xor_sync(0xffffffffu, m, o));
    if ((tid & 31) == 0) red[tid >> 5] = m;
    __syncthreads();
    m = red[0];
    #pragma unroll
    for (int i = 1; i < 8; i++) m = fmaxf(m, red[i]);
    v.x = expf(v.x - m); v.y = expf(v.y - m); v.z = expf(v.z - m); v.w = expf(v.w - m);
    float s = v.x + v.y + v.z + v.w;
    #pragma unroll
    for (int o = 16; o; o >>= 1) s += __shfl_xor_sync(0xffffffffu, s, o);
    __syncthreads();
    if ((tid & 31) == 0) red[tid >> 5] = s;
    __syncthreads();
    s = red[0] + red[1] + red[2] + red[3] + red[4] + red[5] + red[6] + red[7];
    float inv = 1.0f / s;
    v.x *= inv; v.y *= inv; v.z *= inv; v.w *= inv;
    p[tid] = v;
}

// -------- out = LayerNorm(x + y) * g + b.  grid = 2048 rows ----------------------
__global__ void __launch_bounds__(256) add_ln_kernel(
    const float* __restrict__ x, const float* __restrict__ y,
    const float* __restrict__ g, const float* __restrict__ beta,
    float* __restrict__ out)
{
    __shared__ float s1[8], s2[8];
    size_t row = blockIdx.x;
    int tid = threadIdx.x;
    float4 xv = ((const float4*)(x + row * DD))[tid];
    float4 yv = ((const float4*)(y + row * DD))[tid];
    float4 v;
    v.x = xv.x + yv.x; v.y = xv.y + yv.y; v.z = xv.z + yv.z; v.w = xv.w + yv.w;
    float s = v.x + v.y + v.z + v.w;
    float q = v.x * v.x + v.y * v.y + v.z * v.z + v.w * v.w;
    #pragma unroll
    for (int o = 16; o; o >>= 1) {
        s += __shfl_xor_sync(0xffffffffu, s, o);
        q += __shfl_xor_sync(0xffffffffu, q, o);
    }
    if ((tid & 31) == 0) { s1[tid >> 5] = s; s2[tid >> 5] = q; }
    __syncthreads();
    s = s1[0] + s1[1] + s1[2] + s1[3] + s1[4] + s1[5] + s1[6] + s1[7];
    q = s2[0] + s2[1] + s2[2] + s2[3] + s2[4] + s2[5] + s2[6] + s2[7];
    float mean = s * (1.0f / 1024.0f);
    float var = q * (1.0f / 1024.0f) - mean * mean;
    float r = rsqrtf(var + 1e-5f);
    float4 gv = ((const float4*)g)[tid];
    float4 bv = ((const float4*)beta)[tid];
    float4 o;
    o.x = (v.x - mean) * r * gv.x + bv.x;
    o.y = (v.y - mean) * r * gv.y + bv.y;
    o.z = (v.z - mean) * r * gv.z + bv.z;
    o.w = (v.w - mean) * r * gv.w + bv.w;
    ((float4*)(out + row * DD))[tid] = o;
}

// ----------------------------------- host ----------------------------------------
static inline int smem_bytes(int BN, int PREC) {
    int cc = (PREC == 3) ? 2 : 1;
    return (2 * cc * 16 * 128 + 2 * cc * 16 * BN) * 4;
}

extern "C" void kernel_launch(void* const* d_in, const int* in_sizes, int n_in,
                              void* d_out, int out_size)
{
    const float* src = (const float*)d_in[0];
    const float* aux = (const float*)d_in[1];
    const float* Wu  = (const float*)d_in[2];
    const float* bu  = (const float*)d_in[3];
    const float* Wv  = (const float*)d_in[4];
    const float* bv  = (const float*)d_in[5];
    const float* Wo  = (const float*)d_in[6];
    const float* bo  = (const float*)d_in[7];
    const float* W1  = (const float*)d_in[8];
    const float* b1  = (const float*)d_in[9];
    const float* W2  = (const float*)d_in[10];
    const float* b2  = (const float*)d_in[11];
    const float* g1  = (const float*)d_in[12];
    const float* be1 = (const float*)d_in[13];
    const float* g2  = (const float*)d_in[14];
    const float* be2 = (const float*)d_in[15];
    const int* src_mask = (const int*)d_in[16];
    const int* aux_mask = (const int*)d_in[17];

    float *qkv_u, *qkv_v, *Gb, *Hb, *Gpart, *qp, *comb, *attn, *proj, *o1, *ffn, *f2;
    cudaGetSymbolAddress((void**)&qkv_u, g_qkv_u);
    cudaGetSymbolAddress((void**)&qkv_v, g_qkv_v);
    cudaGetSymbolAddress((void**)&Gb, g_G);
    cudaGetSymbolAddress((void**)&Hb, g_H);
    cudaGetSymbolAddress((void**)&Gpart, g_Gpart);
    cudaGetSymbolAddress((void**)&qp, g_qp);
    cudaGetSymbolAddress((void**)&comb, g_comb);
    cudaGetSymbolAddress((void**)&attn, g_attn);
    cudaGetSymbolAddress((void**)&proj, g_proj);
    cudaGetSymbolAddress((void**)&o1, g_o1);
    cudaGetSymbolAddress((void**)&ffn, g_ffn);
    cudaGetSymbolAddress((void**)&f2, g_f2);

    // raise dynamic-smem caps — unconditional (idempotent host-side config;
    // no static guards, identical behavior on every call)
    cudaFuncSetAttribute(mma_gemm<128, 3>, cudaFuncAttributeMaxDynamicSharedMemorySize, smem_bytes(128, 3));
    cudaFuncSetAttribute(mma_gemm<128, 1>, cudaFuncAttributeMaxDynamicSharedMemorySize, smem_bytes(128, 1));
    cudaFuncSetAttribute(mma_gemm<64, 3>,  cudaFuncAttributeMaxDynamicSharedMemorySize, smem_bytes(64, 3));
    cudaFuncSetAttribute(mma_gemm<64, 1>,  cudaFuncAttributeMaxDynamicSharedMemorySize, smem_bytes(64, 1));

    const float inv64 = 1.0f / 64.0f;
    const long long Z = 0;
    const int S128_3 = smem_bytes(128, 3), S128_1 = smem_bytes(128, 1);
    const int S64_3 = smem_bytes(64, 3),   S64_1 = smem_bytes(64, 1);

    // dual-stream QKV projections: Q,K columns at 3xTF32 (logit chain), V at tf32
    mma_gemm<128, 3><<<dim3(16, 16, 1), 256, S128_3>>>(src, 1024, Z, Z, Wu, 3072, Z, Z, 0,
                                                       qkv_u, 3072, Z, Z, 1024, bu, 0, 1.f, (const int*)0);
    mma_gemm<128, 1><<<dim3(8, 16, 1), 256, S128_1>>>(src, 1024, Z, Z, Wu + 2048, 3072, Z, Z, 0,
                                                      qkv_u + 2048, 3072, Z, Z, 1024, bu + 2048, 0, 1.f, (const int*)0);
    mma_gemm<128, 3><<<dim3(16, 16, 1), 256, S128_3>>>(aux, 1024, Z, Z, Wv, 3072, Z, Z, 0,
                                                       qkv_v, 3072, Z, Z, 1024, bv, 0, 1.f, (const int*)0);
    mma_gemm<128, 1><<<dim3(8, 16, 1), 256, S128_1>>>(aux, 1024, Z, Z, Wv + 2048, 3072, Z, Z, 0,
                                                      qkv_v + 2048, 3072, Z, Z, 1024, bv + 2048, 0, 1.f, (const int*)0);

    // G = K_v^T diag(aux_mask) Q_v ; H = K_u^T diag(src_mask) Q_u  (split-K + reduce)
    gmat_part<<<dim3(32, 8), 256>>>(qkv_v, aux_mask, Gpart);
    gmat_reduce<<<dim3(32, 8), 256>>>(Gpart, Gb);
    gmat_part<<<dim3(32, 8), 256>>>(qkv_u, src_mask, Gpart);
    gmat_reduce<<<dim3(32, 8), 256>>>(Gpart, Hb);

    for (int s = 0; s < 2; s++) {
        const float* x   = (s == 0) ? src : aux;
        const float* qkv = (s == 0) ? qkv_u : qkv_v;
        const float* GH  = (s == 0) ? Gb : Hb;
        const int* mk    = (s == 0) ? src_mask : aux_mask;
        float* outp = (float*)d_out + (size_t)s * BT * DD;

        // Q' = Q @ G   (3xTF32, batched per head, N=64)
        mma_gemm<64, 3><<<dim3(1, 8, 32), 256, S64_3>>>(
            qkv, A3, (long long)TT * A3, 64,
            GH, 64, (long long)16 * 4096, 4096, 0,
            qp, DD, (long long)TT * DD, 64,
            64, (const float*)0, 0, 1.f, (const int*)0);

        // comb = (Q' K^T)/64, masked key cols -> 0  (3xTF32, A*B^T)
        mma_gemm<128, 3><<<dim3(8, 8, 32), 256, S128_3>>>(
            qp, DD, (long long)TT * DD, 64,
            qkv + 1024, A3, (long long)TT * A3, 64, 1,
            comb, TT, (long long)16 * TT * TT, (long long)TT * TT,
            64, (const float*)0, 0, inv64, mk);

        softmax_kernel<<<32768, 256>>>(comb);

        // attn = att @ V  (tf32, batched per head, N=64)
        mma_gemm<64, 1><<<dim3(1, 8, 32), 256, S64_1>>>(
            comb, TT, (long long)16 * TT * TT, (long long)TT * TT,
            qkv + 2048, A3, (long long)TT * A3, 64, 0,
            attn, DD, (long long)TT * DD, 64,
            TT, (const float*)0, 0, 1.f, (const int*)0);

        // output projection + LN + FFN + LN  (tf32)
        mma_gemm<128, 1><<<dim3(8, 16, 1), 256, S128_1>>>(attn, 1024, Z, Z, Wo, 1024, Z, Z, 0,
                                                          proj, 1024, Z, Z, 1024, bo, 0, 1.f, (const int*)0);
        add_ln_kernel<<<2048, 256>>>(x, proj, g1, be1, o1);
        mma_gemm<128, 1><<<dim3(32, 16, 1), 256, S128_1>>>(o1, 1024, Z, Z, W1, 4096, Z, Z, 0,
                                                           ffn, 4096, Z, Z, 1024, b1, 1, 1.f, (const int*)0);
        mma_gemm<128, 1><<<dim3(8, 16, 1), 256, S128_1>>>(ffn, 4096, Z, Z, W2, 1024, Z, Z, 0,
                                                          f2, 1024, Z, Z, 4096, b2, 0, 1.f, (const int*)0);
        add_ln_kernel<<<2048, 256>>>(o1, f2, g2, be2, outp);
    }
}

// round 14
// speedup vs baseline: 2.9266x; 1.3016x over previous
#include <cuda_runtime.h>
#include <cstdint>

#define TT 1024      // timesteps
#define DD 1024      // model dim
#define A3 3072      // 3 * attention_dim
#define FF 4096      // feedforward dim
#define BT 2048      // B * T rows
#define NBH 32       // B * H batched heads

// ---------------- scratch (device globals; no allocations allowed) ----------------
__device__ float g_qkv_u[BT * A3];
__device__ float g_qkv_v[BT * A3];
__device__ float g_G[NBH * 4096];
__device__ float g_H[NBH * 4096];
__device__ float g_Gpart[8 * NBH * 4096];
__device__ float g_qp[BT * DD];
__device__ float g_comb[(size_t)NBH * TT * TT];
__device__ float g_attn[BT * DD];
__device__ float g_proj[BT * DD];
__device__ float g_o1[BT * DD];
__device__ float g_ffn[BT * FF];
__device__ float g_f2[BT * DD];
// tf32-rounded copies (producer-side rounding for PREC=1 GEMM operands)
__device__ float g_Wo_r[DD * DD];
__device__ float g_W1_r[DD * FF];
__device__ float g_W2_r[FF * DD];
__device__ float g_WuV_r[DD * DD];
__device__ float g_WvV_r[DD * DD];
__device__ float g_src_r[BT * DD];
__device__ float g_aux_r[BT * DD];

// xor-swizzled smem offset: row k (16 rows), m within row of width W.
#define SWZ(k, m, W) (((k) * (W)) + ((m) ^ (((((k) & 3) ^ (((k) >> 2) & 3))) << 3)))

__device__ __forceinline__ float f2tf32f(float x) {
    unsigned r;
    asm("cvt.rna.tf32.f32 %0, %1;" : "=r"(r) : "f"(x));
    return __uint_as_float(r);
}

#define MMA_TF32(d, a, b)                                                      \
    asm volatile(                                                              \
        "mma.sync.aligned.m16n8k8.row.col.f32.tf32.tf32.f32 "                  \
        "{%0,%1,%2,%3},{%4,%5,%6,%7},{%8,%9},{%0,%1,%2,%3};"                   \
        : "+f"((d)[0]), "+f"((d)[1]), "+f"((d)[2]), "+f"((d)[3])               \
        : "r"((a)[0]), "r"((a)[1]), "r"((a)[2]), "r"((a)[3]),                  \
          "r"((b)[0]), "r"((b)[1]))

#define CP_ASYNC16(dst, src)                                                   \
    asm volatile("cp.async.cg.shared.global [%0], [%1], 16;" :: "r"(dst), "l"(src))
#define CP_COMMIT() asm volatile("cp.async.commit_group;")
#define CP_WAIT(n)  asm volatile("cp.async.wait_group %0;" :: "n"(n))

// ---------------------------------------------------------------------------------
// Tensor-core GEMM: C[M x N] = A[M x K] * B (+bias, relu, scale, col-mask, round)
// BN: 128 or 64. PREC: 1 = tf32 via cp.async 4-stage pipeline; MMA truncation is
//     EXACT because all PREC=1 operands are pre-rounded to tf32 by their producers.
// PREC: 3 = 3xTF32 (fp32-accurate, cvt-at-store double buffer). transB only PREC==3.
// ---------------------------------------------------------------------------------
template <int BN, int PREC>
__global__ void __launch_bounds__(256) mma_gemm(
    const float* __restrict__ A, int lda, long long sAb, long long sAh,
    const float* __restrict__ B, int ldb, long long sBb, long long sBh, int transB,
    float* __restrict__ C, int ldc, long long sCb, long long sCh,
    int K, const float* __restrict__ bias, int relu, float scale,
    const int* __restrict__ mask, int round_out)
{
    constexpr int NF = BN / 16;                 // n-fragments per warp
    constexpr int BF4 = (BN * 16 / 4) / 256;    // float4 chunks per thread for B tile
    constexpr int NH = (NF > 4) ? 2 : 1;        // n-fragment halves
    constexpr int NFH = NF / NH;

    extern __shared__ float sm[];

    int z = blockIdx.z, b = z >> 4, h = z & 15;
    A += (size_t)b * sAb + (size_t)h * sAh;
    B += (size_t)b * sBb + (size_t)h * sBh;
    C += (size_t)b * sCb + (size_t)h * sCh;
    const int* mrow = mask ? (mask + b * TT) : (const int*)0;

    int tid = threadIdx.x, lane = tid & 31, warp = tid >> 5;
    int wy = warp >> 1, wx = warp & 1;
    int wm = wy * 32, wn = wx * (BN / 2);
    int g = lane >> 2, q = lane & 3;
    int m0 = blockIdx.y * 128, n0 = blockIdx.x * BN;

    float acc[2][NF][4];
    #pragma unroll
    for (int mi = 0; mi < 2; mi++)
        #pragma unroll
        for (int nj = 0; nj < NF; nj++)
            #pragma unroll
            for (int e = 0; e < 4; e++) acc[mi][nj][e] = 0.f;

    if constexpr (PREC == 1) {
        // ---------------- cp.async 4-stage pipeline, pre-rounded fp32(tf32) --------
        constexpr int STAGES = 4;
        constexpr int AW = 16 * 128;            // floats per A stage (m-major [m][16])
        constexpr int BW = 16 * BN;             // floats per B stage (k-major [k][BN])
        float* Af = sm;
        float* Bf = sm + STAGES * AW;
        unsigned aBase = (unsigned)__cvta_generic_to_shared(Af);
        unsigned bBase = (unsigned)__cvta_generic_to_shared(Bf);

        auto issue = [&](int slab, int stg) {
            // A tile: 128 rows x 16 k, chunk-swizzled m-major
            #pragma unroll
            for (int i = 0; i < 2; i++) {
                int id = tid + 256 * i;
                int m = id >> 2, c = id & 3;
                const float* src = A + (size_t)(m0 + m) * lda + slab * 16 + c * 4;
                unsigned dst = aBase + (unsigned)(stg * AW + m * 16 + ((c ^ (m & 3)) << 2)) * 4u;
                CP_ASYNC16(dst, src);
            }
            // B tile: 16 k x BN, k-major swizzle
            #pragma unroll
            for (int i = 0; i < BF4; i++) {
                int id = tid + 256 * i;
                int kr = id / (BN / 4), nc4 = (id % (BN / 4)) * 4;
                const float* src = B + (size_t)(slab * 16 + kr) * ldb + n0 + nc4;
                int sw = (((kr & 3) ^ ((kr >> 2) & 3)) << 3);
                unsigned dst = bBase + (unsigned)(stg * BW + kr * BN + (nc4 ^ sw)) * 4u;
                CP_ASYNC16(dst, src);
            }
            CP_COMMIT();
        };

        int nslab = K / 16;
        #pragma unroll
        for (int s = 0; s < STAGES - 1; s++) issue(s, s);

        for (int s = 0; s < nslab; s++) {
            CP_WAIT(STAGES - 2);
            __syncthreads();
            int stg = s & 3;
            const float* pa = Af + stg * AW;
            const float* pb = Bf + stg * BW;

            #pragma unroll
            for (int kk = 0; kk < 16; kk += 8) {
                unsigned ah[2][4];
                #pragma unroll
                for (int mi = 0; mi < 2; mi++) {
                    #pragma unroll
                    for (int e = 0; e < 4; e++) {
                        int m = wm + mi * 16 + g + ((e & 1) ? 8 : 0);
                        int c = (kk >> 2) + ((e >= 2) ? 1 : 0);
                        ah[mi][e] = __float_as_uint(pa[m * 16 + q + ((c ^ (m & 3)) << 2)]);
                    }
                }
                #pragma unroll
                for (int hh = 0; hh < NH; hh++) {
                    unsigned bh[NFH][2];
                    #pragma unroll
                    for (int j = 0; j < NFH; j++) {
                        int n = wn + (hh * NFH + j) * 8 + g;
                        bh[j][0] = __float_as_uint(pb[SWZ(kk + q, n, BN)]);
                        bh[j][1] = __float_as_uint(pb[SWZ(kk + q + 4, n, BN)]);
                    }
                    #pragma unroll
                    for (int mi = 0; mi < 2; mi++)
                        #pragma unroll
                        for (int j = 0; j < NFH; j++)
                            MMA_TF32(acc[mi][hh * NFH + j], ah[mi], bh[j]);
                }
            }

            int nxt = s + STAGES - 1;
            if (nxt < nslab) issue(nxt, nxt & 3);
            else CP_COMMIT();
        }
    } else {
        // ---------------- PREC==3: cvt-at-store hi/lo double buffer ----------------
        constexpr int CC = 2;
        constexpr int AE = 16 * 128;
        constexpr int BE = 16 * BN;
        float* Asm = sm;                    // [2][CC*AE]
        float* Bsm = sm + 2 * CC * AE;      // [2][CC*BE]

        float4 va[2];
        float4 vb[BF4];

        auto loadA = [&](int k0) {
            #pragma unroll
            for (int i = 0; i < 2; i++) {
                int id = tid + 256 * i;
                int r = id >> 2, c4 = (id & 3) * 4;
                va[i] = *(const float4*)&A[(size_t)(m0 + r) * lda + k0 + c4];
            }
        };
        auto storeA = [&](int bf) {
            float* p = Asm + bf * CC * AE;
            #pragma unroll
            for (int i = 0; i < 2; i++) {
                int id = tid + 256 * i;
                int r = id >> 2, c4 = (id & 3) * 4;
                float xs[4] = {va[i].x, va[i].y, va[i].z, va[i].w};
                #pragma unroll
                for (int s = 0; s < 4; s++) {
                    float hi = f2tf32f(xs[s]);
                    p[SWZ(c4 + s, r, 128)] = hi;
                    p[AE + SWZ(c4 + s, r, 128)] = f2tf32f(xs[s] - hi);
                }
            }
        };
        auto loadB = [&](int k0) {
            if (!transB) {
                #pragma unroll
                for (int i = 0; i < BF4; i++) {
                    int id = tid + 256 * i;
                    int kr = id / (BN / 4), nc4 = (id % (BN / 4)) * 4;
                    vb[i] = *(const float4*)&B[(size_t)(k0 + kr) * ldb + n0 + nc4];
                }
            } else {
                #pragma unroll
                for (int i = 0; i < BF4; i++) {
                    int id = tid + 256 * i;
                    int n = id >> 2, c4 = (id & 3) * 4;
                    vb[i] = *(const float4*)&B[(size_t)(n0 + n) * ldb + k0 + c4];
                }
            }
        };
        auto storeB = [&](int bf) {
            float* p = Bsm + bf * CC * BE;
            if (!transB) {
                #pragma unroll
                for (int i = 0; i < BF4; i++) {
                    int id = tid + 256 * i;
                    int kr = id / (BN / 4), nc4 = (id % (BN / 4)) * 4;
                    int sw = (((kr & 3) ^ ((kr >> 2) & 3)) << 3);
                    float xs[4] = {vb[i].x, vb[i].y, vb[i].z, vb[i].w};
                    float4 hv, lv;
                    hv.x = f2tf32f(xs[0]); hv.y = f2tf32f(xs[1]);
                    hv.z = f2tf32f(xs[2]); hv.w = f2tf32f(xs[3]);
                    *(float4*)&p[kr * BN + (nc4 ^ sw)] = hv;
                    lv.x = f2tf32f(xs[0] - hv.x); lv.y = f2tf32f(xs[1] - hv.y);
                    lv.z = f2tf32f(xs[2] - hv.z); lv.w = f2tf32f(xs[3] - hv.w);
                    *(float4*)&p[BE + kr * BN + (nc4 ^ sw)] = lv;
                }
            } else {
                #pragma unroll
                for (int i = 0; i < BF4; i++) {
                    int id = tid + 256 * i;
                    int n = id >> 2, c4 = (id & 3) * 4;
                    float xs[4] = {vb[i].x, vb[i].y, vb[i].z, vb[i].w};
                    #pragma unroll
                    for (int s = 0; s < 4; s++) {
                        float hi = f2tf32f(xs[s]);
                        p[SWZ(c4 + s, n, BN)] = hi;
                        p[BE + SWZ(c4 + s, n, BN)] = f2tf32f(xs[s] - hi);
                    }
                }
            }
        };

        loadA(0); loadB(0);
        storeA(0); storeB(0);
        __syncthreads();

        int buf = 0;
        for (int k0 = 0; k0 < K; k0 += 16) {
            bool more = (k0 + 16) < K;
            if (more) { loadA(k0 + 16); loadB(k0 + 16); }

            const float* pa = Asm + buf * CC * AE;
            const float* pb = Bsm + buf * CC * BE;

            #pragma unroll
            for (int kk = 0; kk < 16; kk += 8) {
                unsigned ah[2][4], al[2][4];
                #pragma unroll
                for (int mi = 0; mi < 2; mi++) {
                    #pragma unroll
                    for (int e = 0; e < 4; e++) {
                        int kq = kk + q + ((e >= 2) ? 4 : 0);
                        int m = wm + mi * 16 + g + ((e & 1) ? 8 : 0);
                        ah[mi][e] = __float_as_uint(pa[SWZ(kq, m, 128)]);
                        al[mi][e] = __float_as_uint(pa[AE + SWZ(kq, m, 128)]);
                    }
                }
                #pragma unroll
                for (int hh = 0; hh < NH; hh++) {
                    unsigned bh[NFH][2], bl[NFH][2];
                    #pragma unroll
                    for (int j = 0; j < NFH; j++) {
                        int n = wn + (hh * NFH + j) * 8 + g;
                        bh[j][0] = __float_as_uint(pb[SWZ(kk + q, n, BN)]);
                        bh[j][1] = __float_as_uint(pb[SWZ(kk + q + 4, n, BN)]);
                        bl[j][0] = __float_as_uint(pb[BE + SWZ(kk + q, n, BN)]);
                        bl[j][1] = __float_as_uint(pb[BE + SWZ(kk + q + 4, n, BN)]);
                    }
                    #pragma unroll
                    for (int mi = 0; mi < 2; mi++)
                        #pragma unroll
                        for (int j = 0; j < NFH; j++) {
                            int nj = hh * NFH + j;
                            MMA_TF32(acc[mi][nj], ah[mi], bh[j]);
                            MMA_TF32(acc[mi][nj], ah[mi], bl[j]);
                            MMA_TF32(acc[mi][nj], al[mi], bh[j]);
                        }
                }
            }

            if (more) {
                storeA(buf ^ 1); storeB(buf ^ 1);
                buf ^= 1;
                __syncthreads();
            }
        }
    }

    // epilogue
    #pragma unroll
    for (int mi = 0; mi < 2; mi++)
        #pragma unroll
        for (int r2 = 0; r2 < 2; r2++) {
            int row = m0 + wm + mi * 16 + g + r2 * 8;
            #pragma unroll
            for (int nj = 0; nj < NF; nj++) {
                int col = n0 + wn + nj * 8 + 2 * q;
                float v0 = acc[mi][nj][r2 * 2 + 0] * scale;
                float v1 = acc[mi][nj][r2 * 2 + 1] * scale;
                if (bias) { v0 += bias[col]; v1 += bias[col + 1]; }
                if (mrow) {
                    if (!mrow[col]) v0 = 0.f;
                    if (!mrow[col + 1]) v1 = 0.f;
                }
                if (relu) { v0 = fmaxf(v0, 0.f); v1 = fmaxf(v1, 0.f); }
                if (round_out) { v0 = f2tf32f(v0); v1 = f2tf32f(v1); }
                float2 o; o.x = v0; o.y = v1;
                *(float2*)&C[(size_t)row * ldc + col] = o;
            }
        }
}

// -------- tf32 round-copy kernels (producer-side rounding of PREC=1 operands) ----
__global__ void __launch_bounds__(256) tf32_round_kernel(
    const float* __restrict__ in, float* __restrict__ out, int n4)
{
    int i = blockIdx.x * 256 + threadIdx.x;
    if (i < n4) {
        float4 v = ((const float4*)in)[i];
        v.x = f2tf32f(v.x); v.y = f2tf32f(v.y); v.z = f2tf32f(v.z); v.w = f2tf32f(v.w);
        ((float4*)out)[i] = v;
    }
}

// rows x 1024 cols from strided source -> contiguous rounded copy. grid (1, rows)
__global__ void __launch_bounds__(256) tf32_round_strided(
    const float* __restrict__ in, float* __restrict__ out, int ld_in)
{
    int r = blockIdx.y;
    int c = threadIdx.x * 4;
    float4 v = *(const float4*)(in + (size_t)r * ld_in + c);
    v.x = f2tf32f(v.x); v.y = f2tf32f(v.y); v.z = f2tf32f(v.z); v.w = f2tf32f(v.w);
    *(float4*)(out + (size_t)r * 1024 + c) = v;
}

// -------- split-K G partials: G = K^T diag(mask) Q per (b,h). grid (32, 8) -------
__global__ void __launch_bounds__(256) gmat_part(
    const float* __restrict__ qkv, const int* __restrict__ mask, float* __restrict__ part)
{
    int z = blockIdx.x; int b = z >> 4; int h = z & 15;
    int tb = blockIdx.y * 128;
    const float* Kb = qkv + (size_t)b * TT * A3 + 1024 + h * 64;
    const float* Qb = qkv + (size_t)b * TT * A3 + h * 64;
    __shared__ float Ks[64][65];
    __shared__ float Qs[64][65];
    int tid = threadIdx.x, tx = tid & 15, ty = tid >> 4;
    float acc[4][4] = {};

    for (int t0 = tb; t0 < tb + 128; t0 += 64) {
        #pragma unroll
        for (int l = 0; l < 4; l++) {
            int lin = tid + l * 256; int r = lin >> 4; int c4 = (lin & 15) * 4;
            int trow = t0 + r;
            float mk = mask[b * TT + trow] ? 1.0f : 0.0f;
            float4 kv = *(const float4*)&Kb[(size_t)trow * A3 + c4];
            Ks[r][c4] = kv.x * mk; Ks[r][c4 + 1] = kv.y * mk;
            Ks[r][c4 + 2] = kv.z * mk; Ks[r][c4 + 3] = kv.w * mk;
            float4 qv = *(const float4*)&Qb[(size_t)trow * A3 + c4];
            Qs[r][c4] = qv.x; Qs[r][c4 + 1] = qv.y; Qs[r][c4 + 2] = qv.z; Qs[r][c4 + 3] = qv.w;
        }
        __syncthreads();
        #pragma unroll
        for (int t = 0; t < 64; t++) {
            float ra[4], rb[4];
            #pragma unroll
            for (int i = 0; i < 4; i++) ra[i] = Ks[t][ty * 4 + i];
            #pragma unroll
            for (int j = 0; j < 4; j++) rb[j] = Qs[t][tx * 4 + j];
            #pragma unroll
            for (int i = 0; i < 4; i++)
                #pragma unroll
                for (int j = 0; j < 4; j++) acc[i][j] = fmaf(ra[i], rb[j], acc[i][j]);
        }
        __syncthreads();
    }
    float* P = part + ((size_t)blockIdx.y * NBH + z) * 4096;
    #pragma unroll
    for (int i = 0; i < 4; i++) {
        float4 o; o.x = acc[i][0]; o.y = acc[i][1]; o.z = acc[i][2]; o.w = acc[i][3];
        *(float4*)&P[(ty * 4 + i) * 64 + tx * 4] = o;
    }
}

// grid (32, 8): each block reduces 512 elements of one head's 64x64 G
__global__ void __launch_bounds__(256) gmat_reduce(
    const float* __restrict__ part, float* __restrict__ G)
{
    int z = blockIdx.x;
    int e = blockIdx.y * 512 + threadIdx.x;
    #pragma unroll
    for (int i = 0; i < 2; i++, e += 256) {
        float s = 0.f;
        #pragma unroll
        for (int k = 0; k < 8; k++) s += part[((size_t)k * NBH + z) * 4096 + e];
        G[(size_t)z * 4096 + e] = s;
    }
}

// -------- row softmax over 1024 cols, in place; output tf32-rounded --------------
__global__ void __launch_bounds__(256) softmax_kernel(float* __restrict__ data)
{
    __shared__ float red[8];
    size_t row = blockIdx.x;
    float4* p = (float4*)(data + row * TT);
    int tid = threadIdx.x;
    float4 v = p[tid];
    float m = fmaxf(fmaxf(v.x, v.y), fmaxf(v.z, v.w));
    #pragma unroll
    for (int o = 16; o; o >>= 1) m = fmaxf(m, __shfl_xor_sync(0xffffffffu, m, o));
    if ((tid & 31) == 0) red[tid >> 5] = m;
    __syncthreads();
    m = red[0];
    #pragma unroll
    for (int i = 1; i < 8; i++) m = fmaxf(m, red[i]);
    v.x = expf(v.x - m); v.y = expf(v.y - m); v.z = expf(v.z - m); v.w = expf(v.w - m);
    float s = v.x + v.y + v.z + v.w;
    #pragma unroll
    for (int o = 16; o; o >>= 1) s += __shfl_xor_sync(0xffffffffu, s, o);
    __syncthreads();
    if ((tid & 31) == 0) red[tid >> 5] = s;
    __syncthreads();
    s = red[0] + red[1] + red[2] + red[3] + red[4] + red[5] + red[6] + red[7];
    float inv = 1.0f / s;
    v.x = f2tf32f(v.x * inv); v.y = f2tf32f(v.y * inv);
    v.z = f2tf32f(v.z * inv); v.w = f2tf32f(v.w * inv);
    p[tid] = v;
}

// -------- out = LayerNorm(x + y) * g + b (optionally tf32-rounded) ---------------
__global__ void __launch_bounds__(256) add_ln_kernel(
    const float* __restrict__ x, const float* __restrict__ y,
    const float* __restrict__ g, const float* __restrict__ beta,
    float* __restrict__ out, int round_out)
{
    __shared__ float s1[8], s2[8];
    size_t row = blockIdx.x;
    int tid = threadIdx.x;
    float4 xv = ((const float4*)(x + row * DD))[tid];
    float4 yv = ((const float4*)(y + row * DD))[tid];
    float4 v;
    v.x = xv.x + yv.x; v.y = xv.y + yv.y; v.z = xv.z + yv.z; v.w = xv.w + yv.w;
    float s = v.x + v.y + v.z + v.w;
    float q = v.x * v.x + v.y * v.y + v.z * v.z + v.w * v.w;
    #pragma unroll
    for (int o = 16; o; o >>= 1) {
        s += __shfl_xor_sync(0xffffffffu, s, o);
        q += __shfl_xor_sync(0xffffffffu, q, o);
    }
    if ((tid & 31) == 0) { s1[tid >> 5] = s; s2[tid >> 5] = q; }
    __syncthreads();
    s = s1[0] + s1[1] + s1[2] + s1[3] + s1[4] + s1[5] + s1[6] + s1[7];
    q = s2[0] + s2[1] + s2[2] + s2[3] + s2[4] + s2[5] + s2[6] + s2[7];
    float mean = s * (1.0f / 1024.0f);
    float var = q * (1.0f / 1024.0f) - mean * mean;
    float r = rsqrtf(var + 1e-5f);
    float4 gv = ((const float4*)g)[tid];
    float4 bv = ((const float4*)beta)[tid];
    float4 o;
    o.x = (v.x - mean) * r * gv.x + bv.x;
    o.y = (v.y - mean) * r * gv.y + bv.y;
    o.z = (v.z - mean) * r * gv.z + bv.z;
    o.w = (v.w - mean) * r * gv.w + bv.w;
    if (round_out) {
        o.x = f2tf32f(o.x); o.y = f2tf32f(o.y);
        o.z = f2tf32f(o.z); o.w = f2tf32f(o.w);
    }
    ((float4*)(out + row * DD))[tid] = o;
}

// ----------------------------------- host ----------------------------------------
static inline int smem_bytes(int BN, int PREC) {
    if (PREC == 1) return 4 * (16 * 128 + 16 * BN) * 4;      // 4-stage cp.async
    return (2 * 2 * 16 * 128 + 2 * 2 * 16 * BN) * 4;         // hi/lo double buffer
}

extern "C" void kernel_launch(void* const* d_in, const int* in_sizes, int n_in,
                              void* d_out, int out_size)
{
    const float* src = (const float*)d_in[0];
    const float* aux = (const float*)d_in[1];
    const float* Wu  = (const float*)d_in[2];
    const float* bu  = (const float*)d_in[3];
    const float* Wv  = (const float*)d_in[4];
    const float* bv  = (const float*)d_in[5];
    const float* Wo  = (const float*)d_in[6];
    const float* bo  = (const float*)d_in[7];
    const float* W1  = (const float*)d_in[8];
    const float* b1  = (const float*)d_in[9];
    const float* W2  = (const float*)d_in[10];
    const float* b2  = (const float*)d_in[11];
    const float* g1  = (const float*)d_in[12];
    const float* be1 = (const float*)d_in[13];
    const float* g2  = (const float*)d_in[14];
    const float* be2 = (const float*)d_in[15];
    const int* src_mask = (const int*)d_in[16];
    const int* aux_mask = (const int*)d_in[17];

    float *qkv_u, *qkv_v, *Gb, *Hb, *Gpart, *qp, *comb, *attn, *proj, *o1, *ffn, *f2;
    float *Wo_r, *W1_r, *W2_r, *WuV_r, *WvV_r, *src_r, *aux_r;
    cudaGetSymbolAddress((void**)&qkv_u, g_qkv_u);
    cudaGetSymbolAddress((void**)&qkv_v, g_qkv_v);
    cudaGetSymbolAddress((void**)&Gb, g_G);
    cudaGetSymbolAddress((void**)&Hb, g_H);
    cudaGetSymbolAddress((void**)&Gpart, g_Gpart);
    cudaGetSymbolAddress((void**)&qp, g_qp);
    cudaGetSymbolAddress((void**)&comb, g_comb);
    cudaGetSymbolAddress((void**)&attn, g_attn);
    cudaGetSymbolAddress((void**)&proj, g_proj);
    cudaGetSymbolAddress((void**)&o1, g_o1);
    cudaGetSymbolAddress((void**)&ffn, g_ffn);
    cudaGetSymbolAddress((void**)&f2, g_f2);
    cudaGetSymbolAddress((void**)&Wo_r, g_Wo_r);
    cudaGetSymbolAddress((void**)&W1_r, g_W1_r);
    cudaGetSymbolAddress((void**)&W2_r, g_W2_r);
    cudaGetSymbolAddress((void**)&WuV_r, g_WuV_r);
    cudaGetSymbolAddress((void**)&WvV_r, g_WvV_r);
    cudaGetSymbolAddress((void**)&src_r, g_src_r);
    cudaGetSymbolAddress((void**)&aux_r, g_aux_r);

    // raise dynamic-smem caps — unconditional (idempotent host-side config)
    cudaFuncSetAttribute(mma_gemm<128, 3>, cudaFuncAttributeMaxDynamicSharedMemorySize, smem_bytes(128, 3));
    cudaFuncSetAttribute(mma_gemm<128, 1>, cudaFuncAttributeMaxDynamicSharedMemorySize, smem_bytes(128, 1));
    cudaFuncSetAttribute(mma_gemm<64, 3>,  cudaFuncAttributeMaxDynamicSharedMemorySize, smem_bytes(64, 3));
    cudaFuncSetAttribute(mma_gemm<64, 1>,  cudaFuncAttributeMaxDynamicSharedMemorySize, smem_bytes(64, 1));

    const float inv64 = 1.0f / 64.0f;
    const long long Z = 0;
    const int S128_3 = smem_bytes(128, 3), S128_1 = smem_bytes(128, 1);
    const int S64_3 = smem_bytes(64, 3),   S64_1 = smem_bytes(64, 1);

    // producer-side tf32 rounding of PREC=1 operands (weights + raw inputs)
    tf32_round_kernel<<<(DD * DD / 4 + 255) / 256, 256>>>(Wo, Wo_r, DD * DD / 4);
    tf32_round_kernel<<<(DD * FF / 4 + 255) / 256, 256>>>(W1, W1_r, DD * FF / 4);
    tf32_round_kernel<<<(FF * DD / 4 + 255) / 256, 256>>>(W2, W2_r, FF * DD / 4);
    tf32_round_kernel<<<(BT * DD / 4 + 255) / 256, 256>>>(src, src_r, BT * DD / 4);
    tf32_round_kernel<<<(BT * DD / 4 + 255) / 256, 256>>>(aux, aux_r, BT * DD / 4);
    tf32_round_strided<<<dim3(1, 1024), 256>>>(Wu + 2048, WuV_r, A3);
    tf32_round_strided<<<dim3(1, 1024), 256>>>(Wv + 2048, WvV_r, A3);

    // dual-stream QKV projections: Q,K columns at 3xTF32 (logit chain), V at tf32
    mma_gemm<128, 3><<<dim3(16, 16, 1), 256, S128_3>>>(src, 1024, Z, Z, Wu, 3072, Z, Z, 0,
                                                       qkv_u, 3072, Z, Z, 1024, bu, 0, 1.f, (const int*)0, 0);
    mma_gemm<128, 1><<<dim3(8, 16, 1), 256, S128_1>>>(src_r, 1024, Z, Z, WuV_r, 1024, Z, Z, 0,
                                                      qkv_u + 2048, 3072, Z, Z, 1024, bu + 2048, 0, 1.f, (const int*)0, 1);
    mma_gemm<128, 3><<<dim3(16, 16, 1), 256, S128_3>>>(aux, 1024, Z, Z, Wv, 3072, Z, Z, 0,
                                                       qkv_v, 3072, Z, Z, 1024, bv, 0, 1.f, (const int*)0, 0);
    mma_gemm<128, 1><<<dim3(8, 16, 1), 256, S128_1>>>(aux_r, 1024, Z, Z, WvV_r, 1024, Z, Z, 0,
                                                      qkv_v + 2048, 3072, Z, Z, 1024, bv + 2048, 0, 1.f, (const int*)0, 1);

    // G = K_v^T diag(aux_mask) Q_v ; H = K_u^T diag(src_mask) Q_u  (split-K + reduce)
    gmat_part<<<dim3(32, 8), 256>>>(qkv_v, aux_mask, Gpart);
    gmat_reduce<<<dim3(32, 8), 256>>>(Gpart, Gb);
    gmat_part<<<dim3(32, 8), 256>>>(qkv_u, src_mask, Gpart);
    gmat_reduce<<<dim3(32, 8), 256>>>(Gpart, Hb);

    for (int s = 0; s < 2; s++) {
        const float* x   = (s == 0) ? src : aux;
        const float* qkv = (s == 0) ? qkv_u : qkv_v;
        const float* GH  = (s == 0) ? Gb : Hb;
        const int* mk    = (s == 0) ? src_mask : aux_mask;
        float* outp = (float*)d_out + (size_t)s * BT * DD;

        // Q' = Q @ G   (3xTF32, batched per head, N=64)
        mma_gemm<64, 3><<<dim3(1, 8, 32), 256, S64_3>>>(
            qkv, A3, (long long)TT * A3, 64,
            GH, 64, (long long)16 * 4096, 4096, 0,
            qp, DD, (long long)TT * DD, 64,
            64, (const float*)0, 0, 1.f, (const int*)0, 0);

        // comb = (Q' K^T)/64, masked key cols -> 0  (3xTF32, A*B^T)
        mma_gemm<128, 3><<<dim3(8, 8, 32), 256, S128_3>>>(
            qp, DD, (long long)TT * DD, 64,
            qkv + 1024, A3, (long long)TT * A3, 64, 1,
            comb, TT, (long long)16 * TT * TT, (long long)TT * TT,
            64, (const float*)0, 0, inv64, mk, 0);

        softmax_kernel<<<32768, 256>>>(comb);

        // attn = att @ V  (tf32, batched per head, N=64; operands pre-rounded)
        mma_gemm<64, 1><<<dim3(1, 8, 32), 256, S64_1>>>(
            comb, TT, (long long)16 * TT * TT, (long long)TT * TT,
            qkv + 2048, A3, (long long)TT * A3, 64, 0,
            attn, DD, (long long)TT * DD, 64,
            TT, (const float*)0, 0, 1.f, (const int*)0, 1);

        // output projection + LN + FFN + LN  (tf32, operands pre-rounded)
        mma_gemm<128, 1><<<dim3(8, 16, 1), 256, S128_1>>>(attn, 1024, Z, Z, Wo_r, 1024, Z, Z, 0,
                                                          proj, 1024, Z, Z, 1024, bo, 0, 1.f, (const int*)0, 0);
        add_ln_kernel<<<2048, 256>>>(x, proj, g1, be1, o1, 1);
        mma_gemm<128, 1><<<dim3(32, 16, 1), 256, S128_1>>>(o1, 1024, Z, Z, W1_r, 4096, Z, Z, 0,
                                                           ffn, 4096, Z, Z, 1024, b1, 1, 1.f, (const int*)0, 1);
        mma_gemm<128, 1><<<dim3(8, 16, 1), 256, S128_1>>>(ffn, 4096, Z, Z, W2_r, 1024, Z, Z, 0,
                                                          f2, 1024, Z, Z, 4096, b2, 0, 1.f, (const int*)0, 0);
        add_ln_kernel<<<2048, 256>>>(o1, f2, g2, be2, outp, 0);
    }
}